// round 1
// baseline (speedup 1.0000x reference)
#include <cuda_runtime.h>
#include <math.h>

// Problem constants
#define BB 8
#define LL 1024
#define HH 8
#define EE 64
#define SS 1024
#define DD 64
#define BH (BB*HH)   // 64

// Static scratch (allocation-free rule: __device__ globals)
__device__ float g_Qp[(size_t)BH * LL * EE];      // 16 MB  phi_p(Q), layout [bh][l][e]
__device__ float g_Kp[(size_t)BH * SS * EE];      // 16 MB  phi_p(K), layout [bh][s][e]
__device__ float g_Sc[(size_t)BH * LL * SS];      // 256 MB scores / attention weights

// ---------------------------------------------------------------------------
// Phase A: phi_p(x) = relu -> power-norm(p=2):  out = (||r||/||r^2||) * r^2
// One warp per 64-element row. flag=0 -> write g_Qp, flag=1 -> write g_Kp.
// Input layout [b][row][h][e]; output layout [bh][row][e].
// ---------------------------------------------------------------------------
__global__ __launch_bounds__(256) void fa_phi_kernel(const float* __restrict__ in, int flag)
{
    int warp = blockIdx.x * 8 + (threadIdx.x >> 5);
    int lane = threadIdx.x & 31;
    int nrows = BB * LL * HH;               // L == S
    if (warp >= nrows) return;

    int b = warp / (LL * HH);
    int l = (warp / HH) % LL;
    int h = warp % HH;

    const float* src = in + (size_t)warp * EE;
    float x0 = fmaxf(src[lane],      0.f);
    float x1 = fmaxf(src[lane + 32], 0.f);
    float a0 = x0 * x0, a1 = x1 * x1;
    float s2 = a0 + a1;                      // sum x^2
    float s4 = a0 * a0 + a1 * a1;            // sum x^4
#pragma unroll
    for (int o = 16; o > 0; o >>= 1) {
        s2 += __shfl_xor_sync(0xffffffffu, s2, o);
        s4 += __shfl_xor_sync(0xffffffffu, s4, o);
    }
    float scale = (s4 > 0.f) ? sqrtf(s2) * rsqrtf(s4) : 0.f;   // ||r|| / ||r^2||

    float* dst = (flag ? g_Kp : g_Qp) + ((size_t)(b * HH + h) * LL + l) * EE;
    dst[lane]      = scale * a0;
    dst[lane + 32] = scale * a1;
}

// ---------------------------------------------------------------------------
// Phase B: scores[bh][l][s] = sum_e Qp[bh][l][e] * Kp[bh][s][e]
// 128x128 tile per CTA, 256 threads, 8x8 microtile, BK=32 (2 k-chunks over E=64)
// ---------------------------------------------------------------------------
__global__ __launch_bounds__(256) void fa_qk_gemm()
{
    __shared__ float As[32][128];
    __shared__ float Bs[32][128];

    int bh = blockIdx.z;
    const float* A  = g_Qp + (size_t)bh * LL * EE;
    const float* Bp = g_Kp + (size_t)bh * SS * EE;
    float*       C  = g_Sc + (size_t)bh * LL * SS;

    int m0 = blockIdx.y * 128;
    int n0 = blockIdx.x * 128;
    int tid = threadIdx.x;
    int tx = tid & 15, ty = tid >> 4;

    float acc[8][8];
#pragma unroll
    for (int i = 0; i < 8; i++)
#pragma unroll
        for (int j = 0; j < 8; j++) acc[i][j] = 0.f;

    for (int k0 = 0; k0 < EE; k0 += 32) {
        // load 128x32 tiles of A and B (transposed into smem: [k][m])
#pragma unroll
        for (int i = 0; i < 4; i++) {
            int idx = tid + i * 256;          // 0..1023 float4 slots
            int row = idx >> 3;               // 8 float4 per row (32 floats)
            int c4  = idx & 7;
            float4 va = *(const float4*)(A  + (size_t)(m0 + row) * EE + k0 + c4 * 4);
            As[c4*4+0][row] = va.x; As[c4*4+1][row] = va.y;
            As[c4*4+2][row] = va.z; As[c4*4+3][row] = va.w;
            float4 vb = *(const float4*)(Bp + (size_t)(n0 + row) * EE + k0 + c4 * 4);
            Bs[c4*4+0][row] = vb.x; Bs[c4*4+1][row] = vb.y;
            Bs[c4*4+2][row] = vb.z; Bs[c4*4+3][row] = vb.w;
        }
        __syncthreads();

#pragma unroll
        for (int k = 0; k < 32; k++) {
            float a[8], bb[8];
            *(float4*)(a)     = *(const float4*)&As[k][ty * 8];
            *(float4*)(a + 4) = *(const float4*)&As[k][ty * 8 + 4];
            *(float4*)(bb)     = *(const float4*)&Bs[k][tx * 8];
            *(float4*)(bb + 4) = *(const float4*)&Bs[k][tx * 8 + 4];
#pragma unroll
            for (int i = 0; i < 8; i++)
#pragma unroll
                for (int j = 0; j < 8; j++)
                    acc[i][j] = fmaf(a[i], bb[j], acc[i][j]);
        }
        __syncthreads();
    }

#pragma unroll
    for (int i = 0; i < 8; i++) {
        float* cp = C + (size_t)(m0 + ty * 8 + i) * SS + n0 + tx * 8;
        *(float4*)(cp)     = make_float4(acc[i][0], acc[i][1], acc[i][2], acc[i][3]);
        *(float4*)(cp + 4) = make_float4(acc[i][4], acc[i][5], acc[i][6], acc[i][7]);
    }
}

// ---------------------------------------------------------------------------
// Phase C: in-place per-row  A = softmax( c * s^2 ),  c = sqrt(sum s^2 / sum s^4)
// One warp per 1024-element row; row held in registers (32 per thread).
// ---------------------------------------------------------------------------
__global__ __launch_bounds__(256) void fa_softmax_kernel()
{
    int row  = blockIdx.x * 8 + (threadIdx.x >> 5);   // over BH*L = 65536 rows
    int lane = threadIdx.x & 31;
    float* p = g_Sc + (size_t)row * SS;

    float v[32];
    float s2 = 0.f, s4 = 0.f, mx = 0.f;
#pragma unroll
    for (int i = 0; i < 32; i++) {
        float s = p[lane + i * 32];
        v[i] = s;
        float a = s * s;
        s2 += a;
        s4 += a * a;
        mx = fmaxf(mx, a);
    }
#pragma unroll
    for (int o = 16; o > 0; o >>= 1) {
        s2 += __shfl_xor_sync(0xffffffffu, s2, o);
        s4 += __shfl_xor_sync(0xffffffffu, s4, o);
        mx  = fmaxf(mx, __shfl_xor_sync(0xffffffffu, mx, o));
    }
    float c = (s4 > 0.f) ? sqrtf(s2) * rsqrtf(s4) : 0.f;
    float m = c * mx;

    float sum = 0.f;
#pragma unroll
    for (int i = 0; i < 32; i++) {
        float e = __expf(fmaf(c * v[i], v[i], -m));   // c*s^2 - m  (<= 0)
        v[i] = e;
        sum += e;
    }
#pragma unroll
    for (int o = 16; o > 0; o >>= 1)
        sum += __shfl_xor_sync(0xffffffffu, sum, o);

    float inv = 1.f / sum;
#pragma unroll
    for (int i = 0; i < 32; i++)
        p[lane + i * 32] = v[i] * inv;
}

// ---------------------------------------------------------------------------
// Phase D: out[b][l][h][d] = sum_s A[bh][l][s] * V[b][s][h][d]
// 128x64 tile per CTA, 256 threads, 8x4 microtile, BK=16
// ---------------------------------------------------------------------------
__global__ __launch_bounds__(256) void fa_av_gemm(const float* __restrict__ Vin,
                                                  float* __restrict__ out)
{
    __shared__ float As[16][128];
    __shared__ float Bs[16][64];

    int bh = blockIdx.z;
    int b = bh >> 3, h = bh & 7;
    const float* A = g_Sc + (size_t)bh * LL * SS;
    int m0 = blockIdx.x * 128;
    int tid = threadIdx.x;
    int tx = tid & 15, ty = tid >> 4;

    float acc[8][4];
#pragma unroll
    for (int i = 0; i < 8; i++)
#pragma unroll
        for (int j = 0; j < 4; j++) acc[i][j] = 0.f;

    for (int k0 = 0; k0 < SS; k0 += 16) {
        // A tile: 128 x 16 -> As[k][m]
#pragma unroll
        for (int i = 0; i < 2; i++) {
            int idx = tid + i * 256;          // 0..511 float4 slots
            int row = idx >> 2;               // 4 float4 per row (16 floats)
            int c4  = idx & 3;
            float4 va = *(const float4*)(A + (size_t)(m0 + row) * SS + k0 + c4 * 4);
            As[c4*4+0][row] = va.x; As[c4*4+1][row] = va.y;
            As[c4*4+2][row] = va.z; As[c4*4+3][row] = va.w;
        }
        // V tile: 16 x 64 (row = s-offset, contiguous d)
        {
            int row = tid >> 4;               // 0..15
            int c4  = tid & 15;               // 0..15
            float4 vb = *(const float4*)(Vin + (((size_t)b * SS + k0 + row) * HH + h) * DD + c4 * 4);
            *(float4*)&Bs[row][c4 * 4] = vb;
        }
        __syncthreads();

#pragma unroll
        for (int k = 0; k < 16; k++) {
            float a[8], bb[4];
            *(float4*)(a)     = *(const float4*)&As[k][ty * 8];
            *(float4*)(a + 4) = *(const float4*)&As[k][ty * 8 + 4];
            *(float4*)(bb)    = *(const float4*)&Bs[k][tx * 4];
#pragma unroll
            for (int i = 0; i < 8; i++)
#pragma unroll
                for (int j = 0; j < 4; j++)
                    acc[i][j] = fmaf(a[i], bb[j], acc[i][j]);
        }
        __syncthreads();
    }

#pragma unroll
    for (int i = 0; i < 8; i++) {
        float4 v0 = make_float4(acc[i][0], acc[i][1], acc[i][2], acc[i][3]);
        *(float4*)(out + (((size_t)b * LL + m0 + ty * 8 + i) * HH + h) * DD + tx * 4) = v0;
    }
}

// ---------------------------------------------------------------------------
extern "C" void kernel_launch(void* const* d_in, const int* in_sizes, int n_in,
                              void* d_out, int out_size)
{
    const float* q = (const float*)d_in[0];   // [B,L,H,E]
    const float* k = (const float*)d_in[1];   // [B,S,H,E]
    const float* v = (const float*)d_in[2];   // [B,S,H,D]
    // d_in[3] = attn_mask, all-False -> no-op
    float* out = (float*)d_out;               // [B,L,H,D]

    fa_phi_kernel<<<8192, 256>>>(q, 0);                 // 65536 rows, 8 warps/CTA
    fa_phi_kernel<<<8192, 256>>>(k, 1);
    fa_qk_gemm<<<dim3(8, 8, BH), 256>>>();              // 128x128 tiles
    fa_softmax_kernel<<<8192, 256>>>();                 // 65536 rows, 8 warps/CTA
    fa_av_gemm<<<dim3(8, 1, BH), 256>>>(v, out);        // 128x64 tiles
}

// round 3
// speedup vs baseline: 1.1719x; 1.1719x over previous
#include <cuda_runtime.h>
#include <math.h>

// Problem constants
#define BB 8
#define LL 1024
#define HH 8
#define EE 64
#define SS 1024
#define DD 64
#define BH (BB*HH)   // 64
#define NROWS (BH*LL) // 65536

// Static scratch (allocation-free rule: __device__ globals)
__device__ float g_Qp[(size_t)BH * LL * EE];      // 16 MB  phi_p(Q), layout [bh][l][e]
__device__ float g_Kp[(size_t)BH * SS * EE];      // 16 MB  phi_p(K), layout [bh][s][e]
__device__ float g_Sc[(size_t)BH * LL * SS];      // 256 MB raw scores
__device__ float g_s2[NROWS];                     // per-row sum s^2
__device__ float g_s4[NROWS];                     // per-row sum s^4
__device__ int   g_mx[NROWS];                     // per-row max s^2 (float bits, >=0)

// ---------------- packed f32x2 helpers (sm_103a FFMA2 — PTX-only path) ------
__device__ __forceinline__ unsigned long long pk2(float x, float y) {
    unsigned long long r;
    asm("mov.b64 %0, {%1, %2};" : "=l"(r) : "f"(x), "f"(y));
    return r;
}
__device__ __forceinline__ void upk2(unsigned long long v, float& x, float& y) {
    asm("mov.b64 {%0, %1}, %2;" : "=f"(x), "=f"(y) : "l"(v));
}
__device__ __forceinline__ void fma2(unsigned long long& d,
                                     unsigned long long a,
                                     unsigned long long b) {
    asm("fma.rn.f32x2 %0, %1, %2, %0;" : "+l"(d) : "l"(a), "l"(b));
}

union F4U { float4 f; unsigned long long u[2]; };

// ---------------------------------------------------------------------------
// Phase A: phi_p for Q (y==0) and K (y==1); Q-side warps also zero row stats.
// ---------------------------------------------------------------------------
__global__ __launch_bounds__(256) void fa_phi_kernel(const float* __restrict__ qin,
                                                     const float* __restrict__ kin)
{
    int warp = blockIdx.x * 8 + (threadIdx.x >> 5);
    int lane = threadIdx.x & 31;
    int isK  = blockIdx.y;
    if (warp >= NROWS) return;

    int b = warp / (LL * HH);
    int l = (warp / HH) % LL;
    int h = warp % HH;

    const float* src = (isK ? kin : qin) + (size_t)warp * EE;
    float x0 = fmaxf(src[lane],      0.f);
    float x1 = fmaxf(src[lane + 32], 0.f);
    float a0 = x0 * x0, a1 = x1 * x1;
    float s2 = a0 + a1;
    float s4 = a0 * a0 + a1 * a1;
#pragma unroll
    for (int o = 16; o > 0; o >>= 1) {
        s2 += __shfl_xor_sync(0xffffffffu, s2, o);
        s4 += __shfl_xor_sync(0xffffffffu, s4, o);
    }
    float scale = (s4 > 0.f) ? sqrtf(s2) * rsqrtf(s4) : 0.f;

    float* dst = (isK ? g_Kp : g_Qp) + ((size_t)(b * HH + h) * LL + l) * EE;
    dst[lane]      = scale * a0;
    dst[lane + 32] = scale * a1;

    if (!isK && lane == 0) {        // zero per-row score stats for this pass
        g_s2[warp] = 0.f;
        g_s4[warp] = 0.f;
        g_mx[warp] = 0;
    }
}

// ---------------------------------------------------------------------------
// Phase B: scores[bh][l][s] = Qp . Kp, writing raw scores + per-row stats.
// 128x128 tile, 256 threads, 8x8 microtile via FFMA2, BK=32.
// ---------------------------------------------------------------------------
__global__ __launch_bounds__(256, 2) void fa_qk_gemm()
{
    __shared__ float As[32][128];
    __shared__ float Bs[32][128];

    int bh = blockIdx.z;
    const float* A  = g_Qp + (size_t)bh * LL * EE;
    const float* Bp = g_Kp + (size_t)bh * SS * EE;
    float*       C  = g_Sc + (size_t)bh * LL * SS;

    int m0 = blockIdx.y * 128;
    int n0 = blockIdx.x * 128;
    int tid = threadIdx.x;
    int tx = tid & 15, ty = tid >> 4;

    unsigned long long acc2[8][4];
    unsigned long long z = pk2(0.f, 0.f);
#pragma unroll
    for (int i = 0; i < 8; i++)
#pragma unroll
        for (int j = 0; j < 4; j++) acc2[i][j] = z;

    for (int k0 = 0; k0 < EE; k0 += 32) {
#pragma unroll
        for (int i = 0; i < 4; i++) {
            int idx = tid + i * 256;
            int row = idx >> 3;
            int c4  = idx & 7;
            float4 va = *(const float4*)(A  + (size_t)(m0 + row) * EE + k0 + c4 * 4);
            As[c4*4+0][row] = va.x; As[c4*4+1][row] = va.y;
            As[c4*4+2][row] = va.z; As[c4*4+3][row] = va.w;
            float4 vb = *(const float4*)(Bp + (size_t)(n0 + row) * EE + k0 + c4 * 4);
            Bs[c4*4+0][row] = vb.x; Bs[c4*4+1][row] = vb.y;
            Bs[c4*4+2][row] = vb.z; Bs[c4*4+3][row] = vb.w;
        }
        __syncthreads();

#pragma unroll
        for (int k = 0; k < 32; k++) {
            float a[8];
            F4U b0, b1;
            *(float4*)(a)     = *(const float4*)&As[k][ty * 8];
            *(float4*)(a + 4) = *(const float4*)&As[k][ty * 8 + 4];
            b0.f = *(const float4*)&Bs[k][tx * 8];
            b1.f = *(const float4*)&Bs[k][tx * 8 + 4];
            unsigned long long bb[4] = { b0.u[0], b0.u[1], b1.u[0], b1.u[1] };
#pragma unroll
            for (int i = 0; i < 8; i++) {
                unsigned long long aa = pk2(a[i], a[i]);
#pragma unroll
                for (int j = 0; j < 4; j++)
                    fma2(acc2[i][j], aa, bb[j]);
            }
        }
        __syncthreads();
    }

    // Epilogue: write raw scores + per-row stats (s2, s4, max s^2)
#pragma unroll
    for (int i = 0; i < 8; i++) {
        float r[8];
#pragma unroll
        for (int j = 0; j < 4; j++) upk2(acc2[i][j], r[j*2], r[j*2+1]);

        float* cp = C + (size_t)(m0 + ty * 8 + i) * SS + n0 + tx * 8;
        *(float4*)(cp)     = make_float4(r[0], r[1], r[2], r[3]);
        *(float4*)(cp + 4) = make_float4(r[4], r[5], r[6], r[7]);

        float ps2 = 0.f, ps4 = 0.f, pmx = 0.f;
#pragma unroll
        for (int j = 0; j < 8; j++) {
            float a = r[j] * r[j];
            ps2 += a;
            ps4 += a * a;
            pmx  = fmaxf(pmx, a);
        }
#pragma unroll
        for (int o = 8; o > 0; o >>= 1) {     // reduce across tx (16-lane group)
            ps2 += __shfl_xor_sync(0xffffffffu, ps2, o);
            ps4 += __shfl_xor_sync(0xffffffffu, ps4, o);
            pmx  = fmaxf(pmx, __shfl_xor_sync(0xffffffffu, pmx, o));
        }
        if (tx == 0) {
            int g = bh * LL + m0 + ty * 8 + i;
            atomicAdd(&g_s2[g], ps2);
            atomicAdd(&g_s4[g], ps4);
            atomicMax(&g_mx[g], __float_as_int(pmx));   // pmx >= 0 -> int order ok
        }
    }
}

// ---------------------------------------------------------------------------
// Phase C: out = softmax-weighted AV, exp applied at A-tile load,
// normalization in the epilogue from loader-accumulated row sums.
// 128x64 tile, 256 threads, 8x4 microtile via FFMA2, BK=16.
// ---------------------------------------------------------------------------
__global__ __launch_bounds__(256, 2) void fa_av_gemm(const float* __restrict__ Vin,
                                                     float* __restrict__ out)
{
    __shared__ float As[16][128];
    __shared__ float Bs[16][64];
    __shared__ float rowsum[128][4];

    int bh = blockIdx.z;
    int b = bh >> 3, h = bh & 7;
    const float* A = g_Sc + (size_t)bh * LL * SS;
    int m0 = blockIdx.x * 128;
    int tid = threadIdx.x;
    int tx = tid & 15, ty = tid >> 4;

    // loader mapping: rows lr0 and lr0+64, 4 consecutive k per chunk at slot c4
    int lr0 = tid >> 2;
    int c4  = tid & 3;
    int g0 = bh * LL + m0 + lr0;
    int g1 = g0 + 64;
    float s2a = g_s2[g0], s4a = g_s4[g0];
    float s2b = g_s2[g1], s4b = g_s4[g1];
    float c0 = (s4a > 0.f) ? sqrtf(s2a) * rsqrtf(s4a) : 0.f;
    float c1 = (s4b > 0.f) ? sqrtf(s2b) * rsqrtf(s4b) : 0.f;
    float mm0 = c0 * __int_as_float(g_mx[g0]);
    float mm1 = c1 * __int_as_float(g_mx[g1]);
    float wa0 = 0.f, wa1 = 0.f;

    unsigned long long acc2[8][2];
    unsigned long long z = pk2(0.f, 0.f);
#pragma unroll
    for (int i = 0; i < 8; i++) { acc2[i][0] = z; acc2[i][1] = z; }

    for (int k0 = 0; k0 < SS; k0 += 16) {
        // A tile rows lr0 / lr0+64, with exp applied; accumulate row sums
        {
            float4 va = *(const float4*)(A + (size_t)(m0 + lr0) * SS + k0 + c4 * 4);
            float w0 = __expf(fmaf(c0 * va.x, va.x, -mm0));
            float w1 = __expf(fmaf(c0 * va.y, va.y, -mm0));
            float w2 = __expf(fmaf(c0 * va.z, va.z, -mm0));
            float w3 = __expf(fmaf(c0 * va.w, va.w, -mm0));
            As[c4*4+0][lr0] = w0; As[c4*4+1][lr0] = w1;
            As[c4*4+2][lr0] = w2; As[c4*4+3][lr0] = w3;
            wa0 += (w0 + w1) + (w2 + w3);

            float4 vc = *(const float4*)(A + (size_t)(m0 + lr0 + 64) * SS + k0 + c4 * 4);
            float u0 = __expf(fmaf(c1 * vc.x, vc.x, -mm1));
            float u1 = __expf(fmaf(c1 * vc.y, vc.y, -mm1));
            float u2 = __expf(fmaf(c1 * vc.z, vc.z, -mm1));
            float u3 = __expf(fmaf(c1 * vc.w, vc.w, -mm1));
            As[c4*4+0][lr0+64] = u0; As[c4*4+1][lr0+64] = u1;
            As[c4*4+2][lr0+64] = u2; As[c4*4+3][lr0+64] = u3;
            wa1 += (u0 + u1) + (u2 + u3);
        }
        // V tile: 16 x 64
        {
            int row = tid >> 4;
            int cc  = tid & 15;
            float4 vb = *(const float4*)(Vin + (((size_t)b * SS + k0 + row) * HH + h) * DD + cc * 4);
            *(float4*)&Bs[row][cc * 4] = vb;
        }
        __syncthreads();

#pragma unroll
        for (int k = 0; k < 16; k++) {
            float a[8];
            F4U bv;
            *(float4*)(a)     = *(const float4*)&As[k][ty * 8];
            *(float4*)(a + 4) = *(const float4*)&As[k][ty * 8 + 4];
            bv.f = *(const float4*)&Bs[k][tx * 4];
#pragma unroll
            for (int i = 0; i < 8; i++) {
                unsigned long long aa = pk2(a[i], a[i]);
                fma2(acc2[i][0], aa, bv.u[0]);
                fma2(acc2[i][1], aa, bv.u[1]);
            }
        }
        __syncthreads();
    }

    rowsum[lr0][c4]      = wa0;
    rowsum[lr0 + 64][c4] = wa1;
    __syncthreads();

#pragma unroll
    for (int i = 0; i < 8; i++) {
        int r = ty * 8 + i;
        float inv = 1.f / (rowsum[r][0] + rowsum[r][1] + rowsum[r][2] + rowsum[r][3]);
        float v0, v1, v2, v3;
        upk2(acc2[i][0], v0, v1);
        upk2(acc2[i][1], v2, v3);
        float4 o = make_float4(v0 * inv, v1 * inv, v2 * inv, v3 * inv);
        *(float4*)(out + (((size_t)b * LL + m0 + r) * HH + h) * DD + tx * 4) = o;
    }
}

// ---------------------------------------------------------------------------
extern "C" void kernel_launch(void* const* d_in, const int* in_sizes, int n_in,
                              void* d_out, int out_size)
{
    const float* q = (const float*)d_in[0];   // [B,L,H,E]
    const float* k = (const float*)d_in[1];   // [B,S,H,E]
    const float* v = (const float*)d_in[2];   // [B,S,H,D]
    float* out = (float*)d_out;               // [B,L,H,D]

    fa_phi_kernel<<<dim3(8192, 2), 256>>>(q, k);
    fa_qk_gemm<<<dim3(8, 8, BH), 256>>>();
    fa_av_gemm<<<dim3(8, 1, BH), 256>>>(v, out);
}

// round 7
// speedup vs baseline: 1.4824x; 1.2650x over previous
#include <cuda_runtime.h>
#include <math.h>
#include <cstdint>

// Problem constants
#define BB 8
#define LL 1024
#define HH 8
#define EE 64
#define SS 1024
#define DD 64
#define BH (BB*HH)    // 64
#define NROWS (BH*LL) // 65536

// Static scratch (allocation-free rule: __device__ globals)
__device__ float g_Qp[(size_t)BH * LL * EE];      // 16 MB  phi_p(Q)  [bh][l][e]
__device__ float g_Kp[(size_t)BH * SS * EE];      // 16 MB  phi_p(K)  [bh][s][e]
__device__ float g_Sc[(size_t)BH * LL * SS];      // 256 MB raw scores
__device__ float g_s2[NROWS];
__device__ float g_s4[NROWS];
__device__ int   g_mx[NROWS];

// ---------------------------------------------------------------------------
// tf32 helpers (arch-portable: sm_80+ PTX, no tcgen05)
// ---------------------------------------------------------------------------
__device__ __forceinline__ uint32_t tf32_rna(float x) {
    uint32_t u;
    asm("cvt.rna.tf32.f32 %0, %1;" : "=r"(u) : "f"(x));
    return u;
}
__device__ __forceinline__ void mma_tf32(float* d, const uint32_t* a, const uint32_t* b) {
    asm volatile(
        "mma.sync.aligned.m16n8k8.row.col.f32.tf32.tf32.f32 "
        "{%0,%1,%2,%3}, {%4,%5,%6,%7}, {%8,%9}, {%0,%1,%2,%3};"
        : "+f"(d[0]), "+f"(d[1]), "+f"(d[2]), "+f"(d[3])
        : "r"(a[0]), "r"(a[1]), "r"(a[2]), "r"(a[3]), "r"(b[0]), "r"(b[1]));
}

// ---------------------------------------------------------------------------
// Phase A: phi_p for Q (y==0) and K (y==1); Q side also zeros row stats.
// ---------------------------------------------------------------------------
__global__ __launch_bounds__(256) void fa_phi_kernel(const float* __restrict__ qin,
                                                     const float* __restrict__ kin)
{
    int warp = blockIdx.x * 8 + (threadIdx.x >> 5);
    int lane = threadIdx.x & 31;
    int isK  = blockIdx.y;
    if (warp >= NROWS) return;

    int b = warp / (LL * HH);
    int l = (warp / HH) % LL;
    int h = warp % HH;

    const float* src = (isK ? kin : qin) + (size_t)warp * EE;
    float x0 = fmaxf(src[lane],      0.f);
    float x1 = fmaxf(src[lane + 32], 0.f);
    float a0 = x0 * x0, a1 = x1 * x1;
    float s2 = a0 + a1;
    float s4 = a0 * a0 + a1 * a1;
#pragma unroll
    for (int o = 16; o > 0; o >>= 1) {
        s2 += __shfl_xor_sync(0xffffffffu, s2, o);
        s4 += __shfl_xor_sync(0xffffffffu, s4, o);
    }
    float scale = (s4 > 0.f) ? sqrtf(s2) * rsqrtf(s4) : 0.f;

    float* dst = (isK ? g_Kp : g_Qp) + ((size_t)(b * HH + h) * LL + l) * EE;
    dst[lane]      = scale * a0;
    dst[lane + 32] = scale * a1;

    if (!isK && lane == 0) {
        g_s2[warp] = 0.f;
        g_s4[warp] = 0.f;
        g_mx[warp] = 0;
    }
}

// ---------------------------------------------------------------------------
// Phase B: QK via mma.sync tf32 (3xTF32). CTA tile 128(M=l) x 128(N=s) x K=64.
// 8 warps (4M x 2N), warp tile 32x64. Writes raw scores + per-row stats.
// ---------------------------------------------------------------------------
#define QK_PAD 68
__global__ __launch_bounds__(256) void fa_qk_mma()
{
    extern __shared__ float sm[];
    float* As = sm;                    // [128][68]
    float* Bs = sm + 128 * QK_PAD;     // [128][68]

    int bh = blockIdx.z;
    int m0 = blockIdx.y * 128, n0 = blockIdx.x * 128;
    const float* A  = g_Qp + (size_t)bh * LL * EE;
    const float* Bp = g_Kp + (size_t)bh * SS * EE;
    float*       C  = g_Sc + (size_t)bh * LL * SS;

    int tid = threadIdx.x, wid = tid >> 5, lane = tid & 31;
    int g = lane >> 2, tg = lane & 3;
    int wm = wid & 3, wn = wid >> 2;

    // Load A[m][k] and B[n][k] tiles (padded, conflict-free fragment LDS)
#pragma unroll
    for (int p = 0; p < 8; p++) {
        int idx = tid + p * 256;       // 0..2047
        int row = idx >> 4, c4 = idx & 15;
        float4 va = *(const float4*)(A  + (size_t)(m0 + row) * EE + c4 * 4);
        *(float4*)&As[row * QK_PAD + c4 * 4] = va;
        float4 vb = *(const float4*)(Bp + (size_t)(n0 + row) * EE + c4 * 4);
        *(float4*)&Bs[row * QK_PAD + c4 * 4] = vb;
    }
    __syncthreads();

    float acc[2][8][4];
#pragma unroll
    for (int mt = 0; mt < 2; mt++)
#pragma unroll
        for (int nt = 0; nt < 8; nt++)
#pragma unroll
            for (int j = 0; j < 4; j++) acc[mt][nt][j] = 0.f;

#pragma unroll
    for (int ks = 0; ks < 8; ks++) {
        int k = ks * 8;
        uint32_t ahi[2][4], alo[2][4];
#pragma unroll
        for (int mt = 0; mt < 2; mt++) {
            int r = wm * 32 + mt * 16 + g;
            float a0 = As[r * QK_PAD + k + tg];
            float a1 = As[(r + 8) * QK_PAD + k + tg];
            float a2 = As[r * QK_PAD + k + tg + 4];
            float a3 = As[(r + 8) * QK_PAD + k + tg + 4];
            ahi[mt][0] = tf32_rna(a0); alo[mt][0] = tf32_rna(a0 - __uint_as_float(ahi[mt][0]));
            ahi[mt][1] = tf32_rna(a1); alo[mt][1] = tf32_rna(a1 - __uint_as_float(ahi[mt][1]));
            ahi[mt][2] = tf32_rna(a2); alo[mt][2] = tf32_rna(a2 - __uint_as_float(ahi[mt][2]));
            ahi[mt][3] = tf32_rna(a3); alo[mt][3] = tf32_rna(a3 - __uint_as_float(ahi[mt][3]));
        }
#pragma unroll
        for (int nt = 0; nt < 8; nt++) {
            int n = wn * 64 + nt * 8 + g;
            float b0 = Bs[n * QK_PAD + k + tg];
            float b1 = Bs[n * QK_PAD + k + tg + 4];
            uint32_t bhi[2], blo[2];
            bhi[0] = tf32_rna(b0); blo[0] = tf32_rna(b0 - __uint_as_float(bhi[0]));
            bhi[1] = tf32_rna(b1); blo[1] = tf32_rna(b1 - __uint_as_float(bhi[1]));
#pragma unroll
            for (int mt = 0; mt < 2; mt++) {
                mma_tf32(acc[mt][nt], ahi[mt], bhi);
                mma_tf32(acc[mt][nt], ahi[mt], blo);
                mma_tf32(acc[mt][nt], alo[mt], bhi);
            }
        }
    }

    // Epilogue: write scores, accumulate per-row stats (s2, s4, max s^2)
#pragma unroll
    for (int mt = 0; mt < 2; mt++) {
        int r0 = wm * 32 + mt * 16 + g;
        int r1 = r0 + 8;
        float s2a = 0.f, s4a = 0.f, mxa = 0.f;
        float s2b = 0.f, s4b = 0.f, mxb = 0.f;
#pragma unroll
        for (int nt = 0; nt < 8; nt++) {
            float* cc = acc[mt][nt];
            float q0 = cc[0] * cc[0]; s2a += q0; s4a += q0 * q0; mxa = fmaxf(mxa, q0);
            float q1 = cc[1] * cc[1]; s2a += q1; s4a += q1 * q1; mxa = fmaxf(mxa, q1);
            float q2 = cc[2] * cc[2]; s2b += q2; s4b += q2 * q2; mxb = fmaxf(mxb, q2);
            float q3 = cc[3] * cc[3]; s2b += q3; s4b += q3 * q3; mxb = fmaxf(mxb, q3);
            int col = n0 + wn * 64 + nt * 8 + tg * 2;
            *(float2*)(C + (size_t)(m0 + r0) * SS + col) = make_float2(cc[0], cc[1]);
            *(float2*)(C + (size_t)(m0 + r1) * SS + col) = make_float2(cc[2], cc[3]);
        }
#pragma unroll
        for (int o = 1; o <= 2; o <<= 1) {      // reduce across tg (4 lanes)
            s2a += __shfl_xor_sync(0xffffffffu, s2a, o);
            s4a += __shfl_xor_sync(0xffffffffu, s4a, o);
            mxa  = fmaxf(mxa, __shfl_xor_sync(0xffffffffu, mxa, o));
            s2b += __shfl_xor_sync(0xffffffffu, s2b, o);
            s4b += __shfl_xor_sync(0xffffffffu, s4b, o);
            mxb  = fmaxf(mxb, __shfl_xor_sync(0xffffffffu, mxb, o));
        }
        if (tg == 0) {
            int ga = bh * LL + m0 + r0;
            atomicAdd(&g_s2[ga], s2a);
            atomicAdd(&g_s4[ga], s4a);
            atomicMax(&g_mx[ga], __float_as_int(mxa));
            int gb = ga + 8;
            atomicAdd(&g_s2[gb], s2b);
            atomicAdd(&g_s4[gb], s4b);
            atomicMax(&g_mx[gb], __float_as_int(mxb));
        }
    }
}

// ---------------------------------------------------------------------------
// Phase C: AV via mma.sync tf32. CTA tile 128(M=l) x 64(N=d), K=S in 64-chunks.
// exp applied in the A loader (weights tf32-rounded BEFORE summing so the
// normalizer matches the MMA operand). Row sums via oct shfl, no atomics.
// ---------------------------------------------------------------------------
#define AV_APAD 68
#define AV_BPAD 68
__global__ __launch_bounds__(256) void fa_av_mma(const float* __restrict__ V,
                                                 float* __restrict__ out)
{
    extern __shared__ float sm[];
    float* Aw     = sm;                              // [128][68] exp weights (tf32)
    float* Bs     = sm + 128 * AV_APAD;              // [64][68]  V tile (tf32)
    float* rowsum = sm + 128 * AV_APAD + 64 * AV_BPAD; // [128]

    int bh = blockIdx.y;
    int b = bh >> 3, h = bh & 7;
    int m0 = blockIdx.x * 128;
    const float* A = g_Sc + (size_t)bh * LL * SS;

    int tid = threadIdx.x, wid = tid >> 5, lane = tid & 31;
    int g = lane >> 2, tg = lane & 3;
    int wm = wid & 3, wn = wid >> 2;

    // loader mapping: 8 threads per row, 4 row-groups of 32
    int lrow = tid >> 3;      // 0..31
    int o8   = tid & 7;       // 0..7
    float cc[4], mm[4];
#pragma unroll
    for (int p = 0; p < 4; p++) {
        int gr = bh * LL + m0 + p * 32 + lrow;
        float s2 = g_s2[gr], s4 = g_s4[gr];
        float c = (s4 > 0.f) ? sqrtf(s2) * rsqrtf(s4) : 0.f;
        cc[p] = c;
        mm[p] = c * __int_as_float(g_mx[gr]);
    }
    float rs[4] = {0.f, 0.f, 0.f, 0.f};

    float acc[2][4][4];
#pragma unroll
    for (int mt = 0; mt < 2; mt++)
#pragma unroll
        for (int nt = 0; nt < 4; nt++)
#pragma unroll
            for (int j = 0; j < 4; j++) acc[mt][nt][j] = 0.f;

    for (int k0 = 0; k0 < SS; k0 += 64) {
        // A tile: exp weights (coalesced 128B per 8-lane group)
#pragma unroll
        for (int p = 0; p < 4; p++) {
            int row = p * 32 + lrow;
            const float* ap = A + (size_t)(m0 + row) * SS + k0;
#pragma unroll
            for (int q = 0; q < 2; q++) {
                int c4 = o8 + q * 8;
                float4 v = *(const float4*)(ap + c4 * 4);
                float w0 = __uint_as_float(tf32_rna(__expf(fmaf(cc[p] * v.x, v.x, -mm[p]))));
                float w1 = __uint_as_float(tf32_rna(__expf(fmaf(cc[p] * v.y, v.y, -mm[p]))));
                float w2 = __uint_as_float(tf32_rna(__expf(fmaf(cc[p] * v.z, v.z, -mm[p]))));
                float w3 = __uint_as_float(tf32_rna(__expf(fmaf(cc[p] * v.w, v.w, -mm[p]))));
                rs[p] += (w0 + w1) + (w2 + w3);
                *(float4*)&Aw[row * AV_APAD + c4 * 4] = make_float4(w0, w1, w2, w3);
            }
        }
        // B tile: V[k0..k0+63][0..63] (k rows, d cols), tf32-rounded
#pragma unroll
        for (int p = 0; p < 4; p++) {
            int idx = tid + p * 256;    // 0..1023
            int r = idx >> 4, c4 = idx & 15;
            float4 v = *(const float4*)(V + (((size_t)b * SS + k0 + r) * HH + h) * DD + c4 * 4);
            v.x = __uint_as_float(tf32_rna(v.x));
            v.y = __uint_as_float(tf32_rna(v.y));
            v.z = __uint_as_float(tf32_rna(v.z));
            v.w = __uint_as_float(tf32_rna(v.w));
            *(float4*)&Bs[r * AV_BPAD + c4 * 4] = v;
        }
        __syncthreads();

#pragma unroll
        for (int ks = 0; ks < 8; ks++) {
            int k = ks * 8;
            uint32_t af[2][4];
#pragma unroll
            for (int mt = 0; mt < 2; mt++) {
                int r = wm * 32 + mt * 16 + g;
                af[mt][0] = __float_as_uint(Aw[r * AV_APAD + k + tg]);
                af[mt][1] = __float_as_uint(Aw[(r + 8) * AV_APAD + k + tg]);
                af[mt][2] = __float_as_uint(Aw[r * AV_APAD + k + tg + 4]);
                af[mt][3] = __float_as_uint(Aw[(r + 8) * AV_APAD + k + tg + 4]);
            }
#pragma unroll
            for (int nt = 0; nt < 4; nt++) {
                int n = wn * 32 + nt * 8 + g;
                uint32_t bf[2];
                bf[0] = __float_as_uint(Bs[(k + tg) * AV_BPAD + n]);
                bf[1] = __float_as_uint(Bs[(k + tg + 4) * AV_BPAD + n]);
#pragma unroll
                for (int mt = 0; mt < 2; mt++)
                    mma_tf32(acc[mt][nt], af[mt], bf);
            }
        }
        __syncthreads();
    }

    // Row sums: reduce over the 8 loader threads per row (oct shfl)
#pragma unroll
    for (int p = 0; p < 4; p++) {
        float v = rs[p];
        v += __shfl_xor_sync(0xffffffffu, v, 1);
        v += __shfl_xor_sync(0xffffffffu, v, 2);
        v += __shfl_xor_sync(0xffffffffu, v, 4);
        if (o8 == 0) rowsum[p * 32 + lrow] = v;
    }
    __syncthreads();

    // Normalize + scatter to out[b][l][h][d]
#pragma unroll
    for (int mt = 0; mt < 2; mt++) {
        int r0 = wm * 32 + mt * 16 + g;
        int r1 = r0 + 8;
        float i0 = 1.f / rowsum[r0];
        float i1 = 1.f / rowsum[r1];
#pragma unroll
        for (int nt = 0; nt < 4; nt++) {
            int col = wn * 32 + nt * 8 + tg * 2;
            float* p0 = out + (((size_t)b * LL + m0 + r0) * HH + h) * DD + col;
            *(float2*)p0 = make_float2(acc[mt][nt][0] * i0, acc[mt][nt][1] * i0);
            float* p1 = out + (((size_t)b * LL + m0 + r1) * HH + h) * DD + col;
            *(float2*)p1 = make_float2(acc[mt][nt][2] * i1, acc[mt][nt][3] * i1);
        }
    }
}

// ---------------------------------------------------------------------------
extern "C" void kernel_launch(void* const* d_in, const int* in_sizes, int n_in,
                              void* d_out, int out_size)
{
    const float* q = (const float*)d_in[0];   // [B,L,H,E]
    const float* k = (const float*)d_in[1];   // [B,S,H,E]
    const float* v = (const float*)d_in[2];   // [B,S,H,D]
    float* out = (float*)d_out;               // [B,L,H,D]

    const int QK_SMEM = 2 * 128 * QK_PAD * 4;                           // 69632
    const int AV_SMEM = (128 * AV_APAD + 64 * AV_BPAD + 128) * 4;       // 52736
    cudaFuncSetAttribute(fa_qk_mma, cudaFuncAttributeMaxDynamicSharedMemorySize, QK_SMEM);
    cudaFuncSetAttribute(fa_av_mma, cudaFuncAttributeMaxDynamicSharedMemorySize, AV_SMEM);

    fa_phi_kernel<<<dim3(8192, 2), 256>>>(q, k);
    fa_qk_mma<<<dim3(8, 8, BH), 256, QK_SMEM>>>();
    fa_av_mma<<<dim3(8, BH), 256, AV_SMEM>>>(v, out);
}

// round 8
// speedup vs baseline: 2.2685x; 1.5303x over previous
#include <cuda_runtime.h>
#include <cuda_fp16.h>
#include <math.h>
#include <cstdint>

// Problem constants
#define BB 8
#define LL 1024
#define HH 8
#define EE 64
#define SS 1024
#define DD 64
#define BH (BB*HH)    // 64
#define NROWS (BH*LL) // 65536

// Static scratch (allocation-free rule: __device__ globals)
// fp16-pair planes: one uint32 packs 2 k-adjacent halves (low 16 = even k).
__device__ uint32_t g_QpH[(size_t)NROWS * 32];    // 8 MB phi(Q) hi  [row][kw]
__device__ uint32_t g_QpL[(size_t)NROWS * 32];    // 8 MB phi(Q) lo
__device__ uint32_t g_KpH[(size_t)NROWS * 32];    // 8 MB phi(K) hi
__device__ uint32_t g_KpL[(size_t)NROWS * 32];    // 8 MB phi(K) lo
__device__ uint32_t g_VtH[(size_t)BH * DD * 512]; // 8 MB V^T fp16 [bh][d][sw]
__device__ float    g_Sc[(size_t)BH * LL * SS];   // 256 MB raw scores (fp32)
__device__ float    g_s2[NROWS];
__device__ float    g_s4[NROWS];
__device__ int      g_mx[NROWS];

// ---------------------------------------------------------------------------
// Helpers
// ---------------------------------------------------------------------------
__device__ __forceinline__ void mma_f16(float* d, const uint32_t* a, const uint32_t* b) {
    asm volatile(
        "mma.sync.aligned.m16n8k16.row.col.f32.f16.f16.f32 "
        "{%0,%1,%2,%3}, {%4,%5,%6,%7}, {%8,%9}, {%0,%1,%2,%3};"
        : "+f"(d[0]), "+f"(d[1]), "+f"(d[2]), "+f"(d[3])
        : "r"(a[0]), "r"(a[1]), "r"(a[2]), "r"(a[3]), "r"(b[0]), "r"(b[1]));
}
__device__ __forceinline__ uint32_t packh2(__half a, __half b) {
    return (uint32_t)__half_as_ushort(a) | ((uint32_t)__half_as_ushort(b) << 16);
}
__device__ __forceinline__ float ex2f(float x) {
    float y;
    asm("ex2.approx.f32 %0, %1;" : "=f"(y) : "f"(x));
    return y;
}
#define LOG2E 1.4426950408889634f

// ---------------------------------------------------------------------------
// Phase A: phi_p for Q (y==0) and K (y==1); outputs fp16 hi/lo planes.
// Lane owns k = 2*lane, 2*lane+1 (one packed word per plane).
// ---------------------------------------------------------------------------
__global__ __launch_bounds__(256) void fa_phi_kernel(const float* __restrict__ qin,
                                                     const float* __restrict__ kin)
{
    int warp = blockIdx.x * 8 + (threadIdx.x >> 5);
    int lane = threadIdx.x & 31;
    int isK  = blockIdx.y;
    if (warp >= NROWS) return;

    int b = warp / (LL * HH);
    int l = (warp / HH) % LL;
    int h = warp % HH;

    const float2* src = (const float2*)((isK ? kin : qin) + (size_t)warp * EE);
    float2 xx = src[lane];
    float x0 = fmaxf(xx.x, 0.f), x1 = fmaxf(xx.y, 0.f);
    float a0 = x0 * x0, a1 = x1 * x1;
    float s2 = a0 + a1;
    float s4 = a0 * a0 + a1 * a1;
#pragma unroll
    for (int o = 16; o > 0; o >>= 1) {
        s2 += __shfl_xor_sync(0xffffffffu, s2, o);
        s4 += __shfl_xor_sync(0xffffffffu, s4, o);
    }
    float scale = (s4 > 0.f) ? sqrtf(s2) * rsqrtf(s4) : 0.f;

    float y0 = scale * a0, y1 = scale * a1;
    __half h0 = __float2half_rn(y0);
    __half h1 = __float2half_rn(y1);
    __half l0 = __float2half_rn(y0 - __half2float(h0));
    __half l1 = __float2half_rn(y1 - __half2float(h1));

    size_t row = (size_t)(b * HH + h) * LL + l;
    uint32_t* dH = (isK ? g_KpH : g_QpH) + row * 32;
    uint32_t* dL = (isK ? g_KpL : g_QpL) + row * 32;
    dH[lane] = packh2(h0, h1);
    dL[lane] = packh2(l0, l1);

    if (!isK && lane == 0) {
        g_s2[warp] = 0.f;
        g_s4[warp] = 0.f;
        g_mx[warp] = 0;
    }
}

// ---------------------------------------------------------------------------
// V transpose + fp16 pack: V[b][s][h][d] -> g_VtH[bh][d][s/2] packed pairs.
// ---------------------------------------------------------------------------
__global__ __launch_bounds__(256) void fa_vt_kernel(const float* __restrict__ V)
{
    __shared__ float sm[64][68];
    int bh = blockIdx.y;
    int b = bh >> 3, h = bh & 7;
    int s0 = blockIdx.x * 64;
    int tid = threadIdx.x;

#pragma unroll
    for (int i = 0; i < 4; i++) {
        int idx = tid + i * 256;
        int sl  = idx >> 4;          // 0..63
        int c4  = idx & 15;          // d float4
        float4 v = *(const float4*)(V + (((size_t)b * SS + s0 + sl) * HH + h) * DD + c4 * 4);
        sm[c4*4+0][sl] = v.x; sm[c4*4+1][sl] = v.y;
        sm[c4*4+2][sl] = v.z; sm[c4*4+3][sl] = v.w;
    }
    __syncthreads();

    uint32_t* dst = g_VtH + (size_t)bh * DD * 512 + (s0 >> 1);
#pragma unroll
    for (int i = 0; i < 8; i++) {
        int idx = tid + i * 256;     // 0..2047
        int d = idx >> 5;            // 0..63
        int w = idx & 31;            // word within 64-s block
        dst[(size_t)d * 512 + w] = packh2(__float2half_rn(sm[d][2*w]),
                                          __float2half_rn(sm[d][2*w + 1]));
    }
}

// ---------------------------------------------------------------------------
// Phase B: QK via mma.sync fp16 (3-pass hi/lo split).
// CTA tile 128(M=l) x 128(N=s) x K=64, 8 warps (4M x 2N), warp tile 32x64.
// Writes raw fp32 scores + per-row stats.
// ---------------------------------------------------------------------------
#define KPAD 36   // uint32 words per row (32 data + 4 pad): (4g+tg) distinct mod 32
__global__ __launch_bounds__(256) void fa_qk_mma()
{
    extern __shared__ uint32_t sw[];
    uint32_t* AH = sw;                 // [128][36]
    uint32_t* AL = sw + 128 * KPAD;
    uint32_t* BHs = sw + 2 * 128 * KPAD;
    uint32_t* BLs = sw + 3 * 128 * KPAD;

    int bh = blockIdx.z;
    int m0 = blockIdx.y * 128, n0 = blockIdx.x * 128;
    const uint32_t* qh = g_QpH + (size_t)bh * LL * 32;
    const uint32_t* ql = g_QpL + (size_t)bh * LL * 32;
    const uint32_t* kh = g_KpH + (size_t)bh * SS * 32;
    const uint32_t* kl = g_KpL + (size_t)bh * SS * 32;
    float* C = g_Sc + (size_t)bh * LL * SS;

    int tid = threadIdx.x, wid = tid >> 5, lane = tid & 31;
    int g = lane >> 2, tg = lane & 3;
    int wm = wid & 3, wn = wid >> 2;

    // Load 4 planes: 128 rows x 8 uint4 each
#pragma unroll
    for (int p = 0; p < 4; p++) {
        int idx = tid + p * 256;       // 0..1023
        int row = idx >> 3, c4 = idx & 7;
        size_t go = (size_t)(m0 + row) * 32 + c4 * 4;
        size_t gk = (size_t)(n0 + row) * 32 + c4 * 4;
        *(uint4*)&AH [row * KPAD + c4 * 4] = *(const uint4*)(qh + go);
        *(uint4*)&AL [row * KPAD + c4 * 4] = *(const uint4*)(ql + go);
        *(uint4*)&BHs[row * KPAD + c4 * 4] = *(const uint4*)(kh + gk);
        *(uint4*)&BLs[row * KPAD + c4 * 4] = *(const uint4*)(kl + gk);
    }
    __syncthreads();

    float acc[2][8][4];
#pragma unroll
    for (int mt = 0; mt < 2; mt++)
#pragma unroll
        for (int nt = 0; nt < 8; nt++)
#pragma unroll
            for (int j = 0; j < 4; j++) acc[mt][nt][j] = 0.f;

#pragma unroll
    for (int ks = 0; ks < 4; ks++) {
        int kw = ks * 8;
        uint32_t ahi[2][4], alo[2][4];
#pragma unroll
        for (int mt = 0; mt < 2; mt++) {
            int r = wm * 32 + mt * 16 + g;
            ahi[mt][0] = AH[r * KPAD + kw + tg];
            ahi[mt][1] = AH[(r + 8) * KPAD + kw + tg];
            ahi[mt][2] = AH[r * KPAD + kw + tg + 4];
            ahi[mt][3] = AH[(r + 8) * KPAD + kw + tg + 4];
            alo[mt][0] = AL[r * KPAD + kw + tg];
            alo[mt][1] = AL[(r + 8) * KPAD + kw + tg];
            alo[mt][2] = AL[r * KPAD + kw + tg + 4];
            alo[mt][3] = AL[(r + 8) * KPAD + kw + tg + 4];
        }
#pragma unroll
        for (int nt = 0; nt < 8; nt++) {
            int n = wn * 64 + nt * 8 + g;
            uint32_t bhi[2], blo[2];
            bhi[0] = BHs[n * KPAD + kw + tg];
            bhi[1] = BHs[n * KPAD + kw + tg + 4];
            blo[0] = BLs[n * KPAD + kw + tg];
            blo[1] = BLs[n * KPAD + kw + tg + 4];
#pragma unroll
            for (int mt = 0; mt < 2; mt++) {
                mma_f16(acc[mt][nt], ahi[mt], bhi);
                mma_f16(acc[mt][nt], ahi[mt], blo);
                mma_f16(acc[mt][nt], alo[mt], bhi);
            }
        }
    }

    // Epilogue: write fp32 scores, accumulate per-row stats
#pragma unroll
    for (int mt = 0; mt < 2; mt++) {
        int r0 = wm * 32 + mt * 16 + g;
        int r1 = r0 + 8;
        float s2a = 0.f, s4a = 0.f, mxa = 0.f;
        float s2b = 0.f, s4b = 0.f, mxb = 0.f;
#pragma unroll
        for (int nt = 0; nt < 8; nt++) {
            float* cc = acc[mt][nt];
            float q0 = cc[0] * cc[0]; s2a += q0; s4a += q0 * q0; mxa = fmaxf(mxa, q0);
            float q1 = cc[1] * cc[1]; s2a += q1; s4a += q1 * q1; mxa = fmaxf(mxa, q1);
            float q2 = cc[2] * cc[2]; s2b += q2; s4b += q2 * q2; mxb = fmaxf(mxb, q2);
            float q3 = cc[3] * cc[3]; s2b += q3; s4b += q3 * q3; mxb = fmaxf(mxb, q3);
            int col = n0 + wn * 64 + nt * 8 + tg * 2;
            *(float2*)(C + (size_t)(m0 + r0) * SS + col) = make_float2(cc[0], cc[1]);
            *(float2*)(C + (size_t)(m0 + r1) * SS + col) = make_float2(cc[2], cc[3]);
        }
#pragma unroll
        for (int o = 1; o <= 2; o <<= 1) {
            s2a += __shfl_xor_sync(0xffffffffu, s2a, o);
            s4a += __shfl_xor_sync(0xffffffffu, s4a, o);
            mxa  = fmaxf(mxa, __shfl_xor_sync(0xffffffffu, mxa, o));
            s2b += __shfl_xor_sync(0xffffffffu, s2b, o);
            s4b += __shfl_xor_sync(0xffffffffu, s4b, o);
            mxb  = fmaxf(mxb, __shfl_xor_sync(0xffffffffu, mxb, o));
        }
        if (tg == 0) {
            int ga = bh * LL + m0 + r0;
            atomicAdd(&g_s2[ga], s2a);
            atomicAdd(&g_s4[ga], s4a);
            atomicMax(&g_mx[ga], __float_as_int(mxa));
            int gb = ga + 8;
            atomicAdd(&g_s2[gb], s2b);
            atomicAdd(&g_s4[gb], s4b);
            atomicMax(&g_mx[gb], __float_as_int(mxb));
        }
    }
}

// ---------------------------------------------------------------------------
// Phase C: AV via mma.sync fp16. CTA tile 128(M=l) x 64(N=d), K=S in 64-chunks.
// exp2 applied in the A loader; weights fp16-rounded BEFORE summing so the
// normalizer matches the MMA operand. Row sums via oct shfl.
// ---------------------------------------------------------------------------
__global__ __launch_bounds__(256) void fa_av_mma(float* __restrict__ out)
{
    extern __shared__ uint32_t sw[];
    uint32_t* Aw = sw;                       // [128][36] fp16-pair weights
    uint32_t* Bs = sw + 128 * KPAD;          // [64][36]  fp16-pair V^T
    float* rowsum = (float*)(sw + 128 * KPAD + 64 * KPAD);   // [128]

    int bh = blockIdx.y;
    int b = bh >> 3, h = bh & 7;
    int m0 = blockIdx.x * 128;
    const float* A = g_Sc + (size_t)bh * LL * SS;
    const uint32_t* Vt = g_VtH + (size_t)bh * DD * 512;

    int tid = threadIdx.x, wid = tid >> 5, lane = tid & 31;
    int g = lane >> 2, tg = lane & 3;
    int wm = wid & 3, wn = wid >> 2;

    // loader mapping: 8 threads per row, 4 row-groups of 32
    int lrow = tid >> 3;      // 0..31
    int o8   = tid & 7;       // 0..7
    float cc[4], mm[4];
#pragma unroll
    for (int p = 0; p < 4; p++) {
        int gr = bh * LL + m0 + p * 32 + lrow;
        float s2 = g_s2[gr], s4 = g_s4[gr];
        float c = (s4 > 0.f) ? sqrtf(s2) * rsqrtf(s4) : 0.f;
        cc[p] = c * LOG2E;
        mm[p] = cc[p] * __int_as_float(g_mx[gr]);
    }
    float rs[4] = {0.f, 0.f, 0.f, 0.f};

    float acc[2][4][4];
#pragma unroll
    for (int mt = 0; mt < 2; mt++)
#pragma unroll
        for (int nt = 0; nt < 4; nt++)
#pragma unroll
            for (int j = 0; j < 4; j++) acc[mt][nt][j] = 0.f;

    for (int k0 = 0; k0 < SS; k0 += 64) {
        // A tile: exp2 weights -> fp16 pairs
#pragma unroll
        for (int p = 0; p < 4; p++) {
            int row = p * 32 + lrow;
            const float* ap = A + (size_t)(m0 + row) * SS + k0;
#pragma unroll
            for (int q = 0; q < 2; q++) {
                int c4 = o8 + q * 8;          // float4 index: k = 4c4..4c4+3
                float4 v = *(const float4*)(ap + c4 * 4);
                __half h0 = __float2half_rn(ex2f(fmaf(cc[p] * v.x, v.x, -mm[p])));
                __half h1 = __float2half_rn(ex2f(fmaf(cc[p] * v.y, v.y, -mm[p])));
                __half h2 = __float2half_rn(ex2f(fmaf(cc[p] * v.z, v.z, -mm[p])));
                __half h3 = __float2half_rn(ex2f(fmaf(cc[p] * v.w, v.w, -mm[p])));
                rs[p] += (__half2float(h0) + __half2float(h1))
                       + (__half2float(h2) + __half2float(h3));
                uint2 w2 = make_uint2(packh2(h0, h1), packh2(h2, h3));
                *(uint2*)&Aw[row * KPAD + 2 * c4] = w2;
            }
        }
        // B tile: Vt[d][sw] words for this chunk: 64 rows x 8 uint4
#pragma unroll
        for (int p = 0; p < 2; p++) {
            int idx = tid + p * 256;      // 0..511
            int d = idx >> 3, c4 = idx & 7;
            *(uint4*)&Bs[d * KPAD + c4 * 4] =
                *(const uint4*)(Vt + (size_t)d * 512 + (k0 >> 1) + c4 * 4);
        }
        __syncthreads();

#pragma unroll
        for (int ks = 0; ks < 4; ks++) {
            int kw = ks * 8;
            uint32_t af[2][4];
#pragma unroll
            for (int mt = 0; mt < 2; mt++) {
                int r = wm * 32 + mt * 16 + g;
                af[mt][0] = Aw[r * KPAD + kw + tg];
                af[mt][1] = Aw[(r + 8) * KPAD + kw + tg];
                af[mt][2] = Aw[r * KPAD + kw + tg + 4];
                af[mt][3] = Aw[(r + 8) * KPAD + kw + tg + 4];
            }
#pragma unroll
            for (int nt = 0; nt < 4; nt++) {
                int n = wn * 32 + nt * 8 + g;
                uint32_t bf[2];
                bf[0] = Bs[n * KPAD + kw + tg];
                bf[1] = Bs[n * KPAD + kw + tg + 4];
#pragma unroll
                for (int mt = 0; mt < 2; mt++)
                    mma_f16(acc[mt][nt], af[mt], bf);
            }
        }
        __syncthreads();
    }

    // Row sums: reduce over the 8 loader threads per row (oct shfl)
#pragma unroll
    for (int p = 0; p < 4; p++) {
        float v = rs[p];
        v += __shfl_xor_sync(0xffffffffu, v, 1);
        v += __shfl_xor_sync(0xffffffffu, v, 2);
        v += __shfl_xor_sync(0xffffffffu, v, 4);
        if (o8 == 0) rowsum[p * 32 + lrow] = v;
    }
    __syncthreads();

    // Normalize + scatter to out[b][l][h][d]
#pragma unroll
    for (int mt = 0; mt < 2; mt++) {
        int r0 = wm * 32 + mt * 16 + g;
        int r1 = r0 + 8;
        float i0 = 1.f / rowsum[r0];
        float i1 = 1.f / rowsum[r1];
#pragma unroll
        for (int nt = 0; nt < 4; nt++) {
            int col = wn * 32 + nt * 8 + tg * 2;
            float* p0 = out + (((size_t)b * LL + m0 + r0) * HH + h) * DD + col;
            *(float2*)p0 = make_float2(acc[mt][nt][0] * i0, acc[mt][nt][1] * i0);
            float* p1 = out + (((size_t)b * LL + m0 + r1) * HH + h) * DD + col;
            *(float2*)p1 = make_float2(acc[mt][nt][2] * i1, acc[mt][nt][3] * i1);
        }
    }
}

// ---------------------------------------------------------------------------
extern "C" void kernel_launch(void* const* d_in, const int* in_sizes, int n_in,
                              void* d_out, int out_size)
{
    const float* q = (const float*)d_in[0];   // [B,L,H,E]
    const float* k = (const float*)d_in[1];   // [B,S,H,E]
    const float* v = (const float*)d_in[2];   // [B,S,H,D]
    float* out = (float*)d_out;               // [B,L,H,D]

    const int QK_SMEM = 4 * 128 * KPAD * 4;                   // 73728
    const int AV_SMEM = (128 * KPAD + 64 * KPAD + 128) * 4;   // 28160
    cudaFuncSetAttribute(fa_qk_mma, cudaFuncAttributeMaxDynamicSharedMemorySize, QK_SMEM);
    cudaFuncSetAttribute(fa_av_mma, cudaFuncAttributeMaxDynamicSharedMemorySize, AV_SMEM);

    fa_phi_kernel<<<dim3(8192, 2), 256>>>(q, k);
    fa_vt_kernel<<<dim3(16, BH), 256>>>(v);
    fa_qk_mma<<<dim3(8, 8, BH), 256, QK_SMEM>>>();
    fa_av_mma<<<dim3(8, BH), 256, AV_SMEM>>>(out);
}

// round 10
// speedup vs baseline: 2.8224x; 1.2442x over previous
#include <cuda_runtime.h>
#include <cuda_fp16.h>
#include <math.h>
#include <cstdint>

// Problem constants
#define BB 8
#define LL 1024
#define HH 8
#define EE 64
#define SS 1024
#define DD 64
#define BH (BB*HH)    // 64
#define NROWS (BH*LL) // 65536

// Static scratch (allocation-free rule: __device__ globals)
__device__ uint32_t g_QpH[(size_t)NROWS * 32];    // phi(Q) hi  fp16-pairs [row][kw]
__device__ uint32_t g_QpL[(size_t)NROWS * 32];    // phi(Q) lo
__device__ uint32_t g_KpH[(size_t)NROWS * 32];    // phi(K) hi
__device__ uint32_t g_KpL[(size_t)NROWS * 32];    // phi(K) lo
__device__ uint32_t g_VtH[(size_t)BH * DD * 512]; // V^T fp16 [bh][d][sw]
__device__ float    g_Sc[(size_t)BH * LL * SS];   // 256 MB raw scores (fp32)
__device__ float    g_s2[NROWS];
__device__ float    g_s4[NROWS];
__device__ int      g_mx[NROWS];

// ---------------------------------------------------------------------------
// Helpers
// ---------------------------------------------------------------------------
__device__ __forceinline__ void mma_f16(float* d, const uint32_t* a, const uint32_t* b) {
    asm volatile(
        "mma.sync.aligned.m16n8k16.row.col.f32.f16.f16.f32 "
        "{%0,%1,%2,%3}, {%4,%5,%6,%7}, {%8,%9}, {%0,%1,%2,%3};"
        : "+f"(d[0]), "+f"(d[1]), "+f"(d[2]), "+f"(d[3])
        : "r"(a[0]), "r"(a[1]), "r"(a[2]), "r"(a[3]), "r"(b[0]), "r"(b[1]));
}
__device__ __forceinline__ void ldm_x4(uint32_t* r, uint32_t a) {
    asm volatile("ldmatrix.sync.aligned.m8n8.x4.shared.b16 {%0,%1,%2,%3}, [%4];"
        : "=r"(r[0]), "=r"(r[1]), "=r"(r[2]), "=r"(r[3]) : "r"(a));
}
__device__ __forceinline__ uint32_t smem_u32(const void* p) {
    uint32_t a;
    asm("{ .reg .u64 t; cvta.to.shared.u64 t, %1; cvt.u32.u64 %0, t; }" : "=r"(a) : "l"(p));
    return a;
}
__device__ __forceinline__ void cp16(uint32_t sdst, const void* gsrc) {
    asm volatile("cp.async.cg.shared.global [%0], [%1], 16;" :: "r"(sdst), "l"(gsrc));
}
__device__ __forceinline__ void cp_commit() {
    asm volatile("cp.async.commit_group;" ::: "memory");
}
#define CP_WAIT(N) asm volatile("cp.async.wait_group %0;" :: "n"(N) : "memory")

__device__ __forceinline__ uint32_t packh2(__half a, __half b) {
    return (uint32_t)__half_as_ushort(a) | ((uint32_t)__half_as_ushort(b) << 16);
}
__device__ __forceinline__ float ex2f(float x) {
    float y;
    asm("ex2.approx.f32 %0, %1;" : "=f"(y) : "f"(x));
    return y;
}
#define LOG2E 1.4426950408889634f
#define KPAD 36   // uint32 words per fp16 row (32 data + 4 pad)

// ---------------------------------------------------------------------------
// Phase A: phi_p for Q (y==0) and K (y==1); outputs fp16 hi/lo planes.
// ---------------------------------------------------------------------------
__global__ __launch_bounds__(256) void fa_phi_kernel(const float* __restrict__ qin,
                                                     const float* __restrict__ kin)
{
    int warp = blockIdx.x * 8 + (threadIdx.x >> 5);
    int lane = threadIdx.x & 31;
    int isK  = blockIdx.y;
    if (warp >= NROWS) return;

    int b = warp / (LL * HH);
    int l = (warp / HH) % LL;
    int h = warp % HH;

    const float2* src = (const float2*)((isK ? kin : qin) + (size_t)warp * EE);
    float2 xx = src[lane];
    float x0 = fmaxf(xx.x, 0.f), x1 = fmaxf(xx.y, 0.f);
    float a0 = x0 * x0, a1 = x1 * x1;
    float s2 = a0 + a1;
    float s4 = a0 * a0 + a1 * a1;
#pragma unroll
    for (int o = 16; o > 0; o >>= 1) {
        s2 += __shfl_xor_sync(0xffffffffu, s2, o);
        s4 += __shfl_xor_sync(0xffffffffu, s4, o);
    }
    float scale = (s4 > 0.f) ? sqrtf(s2) * rsqrtf(s4) : 0.f;

    float y0 = scale * a0, y1 = scale * a1;
    __half h0 = __float2half_rn(y0);
    __half h1 = __float2half_rn(y1);
    __half l0 = __float2half_rn(y0 - __half2float(h0));
    __half l1 = __float2half_rn(y1 - __half2float(h1));

    size_t row = (size_t)(b * HH + h) * LL + l;
    uint32_t* dH = (isK ? g_KpH : g_QpH) + row * 32;
    uint32_t* dL = (isK ? g_KpL : g_QpL) + row * 32;
    dH[lane] = packh2(h0, h1);
    dL[lane] = packh2(l0, l1);

    if (!isK && lane == 0) {
        g_s2[warp] = 0.f;
        g_s4[warp] = 0.f;
        g_mx[warp] = 0;
    }
}

// ---------------------------------------------------------------------------
// V transpose + fp16 pack: V[b][s][h][d] -> g_VtH[bh][d][s/2] packed pairs.
// ---------------------------------------------------------------------------
__global__ __launch_bounds__(256) void fa_vt_kernel(const float* __restrict__ V)
{
    __shared__ float sm[64][68];
    int bh = blockIdx.y;
    int b = bh >> 3, h = bh & 7;
    int s0 = blockIdx.x * 64;
    int tid = threadIdx.x;

#pragma unroll
    for (int i = 0; i < 4; i++) {
        int idx = tid + i * 256;
        int sl  = idx >> 4;
        int c4  = idx & 15;
        float4 v = *(const float4*)(V + (((size_t)b * SS + s0 + sl) * HH + h) * DD + c4 * 4);
        sm[c4*4+0][sl] = v.x; sm[c4*4+1][sl] = v.y;
        sm[c4*4+2][sl] = v.z; sm[c4*4+3][sl] = v.w;
    }
    __syncthreads();

    uint32_t* dst = g_VtH + (size_t)bh * DD * 512 + (s0 >> 1);
#pragma unroll
    for (int i = 0; i < 8; i++) {
        int idx = tid + i * 256;
        int d = idx >> 5;
        int w = idx & 31;
        dst[(size_t)d * 512 + w] = packh2(__float2half_rn(sm[d][2*w]),
                                          __float2half_rn(sm[d][2*w + 1]));
    }
}

// ---------------------------------------------------------------------------
// Phase B: QK via mma.sync fp16 (3-pass hi/lo split), ldmatrix fragment loads.
// CTA tile 128(M=l) x 128(N=s) x K=64, 8 warps (4M x 2N), warp tile 32x64.
// ---------------------------------------------------------------------------
__global__ __launch_bounds__(256) void fa_qk_mma()
{
    extern __shared__ uint32_t sw[];
    uint32_t* AH  = sw;                   // [128][36]
    uint32_t* AL  = sw + 128 * KPAD;
    uint32_t* BHs = sw + 2 * 128 * KPAD;
    uint32_t* BLs = sw + 3 * 128 * KPAD;

    int bh = blockIdx.z;
    int m0 = blockIdx.y * 128, n0 = blockIdx.x * 128;
    const uint32_t* qh = g_QpH + (size_t)bh * LL * 32;
    const uint32_t* ql = g_QpL + (size_t)bh * LL * 32;
    const uint32_t* kh = g_KpH + (size_t)bh * SS * 32;
    const uint32_t* kl = g_KpL + (size_t)bh * SS * 32;
    float* C = g_Sc + (size_t)bh * LL * SS;

    int tid = threadIdx.x, wid = tid >> 5, lane = tid & 31;
    int g = lane >> 2, tg = lane & 3;
    int wm = wid & 3, wn = wid >> 2;

    // Load 4 planes: 128 rows x 8 uint4 each
#pragma unroll
    for (int p = 0; p < 4; p++) {
        int idx = tid + p * 256;
        int row = idx >> 3, c4 = idx & 7;
        size_t go = (size_t)(m0 + row) * 32 + c4 * 4;
        size_t gk = (size_t)(n0 + row) * 32 + c4 * 4;
        *(uint4*)&AH [row * KPAD + c4 * 4] = *(const uint4*)(qh + go);
        *(uint4*)&AL [row * KPAD + c4 * 4] = *(const uint4*)(ql + go);
        *(uint4*)&BHs[row * KPAD + c4 * 4] = *(const uint4*)(kh + gk);
        *(uint4*)&BLs[row * KPAD + c4 * 4] = *(const uint4*)(kl + gk);
    }
    __syncthreads();

    uint32_t sb = smem_u32(sw);
    uint32_t aAH = sb;
    uint32_t aAL = sb + 128 * KPAD * 4;
    uint32_t aBH = sb + 2 * 128 * KPAD * 4;
    uint32_t aBL = sb + 3 * 128 * KPAD * 4;

    // per-lane ldmatrix byte offsets (within a plane)
    int arow = wm * 32 + (lane & 15);
    uint32_t aoff = (uint32_t)(arow * KPAD + ((lane >> 4) << 2)) * 4;
    int brow = wn * 64 + ((lane >> 4) << 3) + (lane & 7);
    uint32_t boff = (uint32_t)(brow * KPAD + (((lane >> 3) & 1) << 2)) * 4;

    float acc[2][8][4];
#pragma unroll
    for (int mt = 0; mt < 2; mt++)
#pragma unroll
        for (int nt = 0; nt < 8; nt++)
#pragma unroll
            for (int j = 0; j < 4; j++) acc[mt][nt][j] = 0.f;

#pragma unroll
    for (int ks = 0; ks < 4; ks++) {
        uint32_t kb = ks * 32;       // byte offset: 8 words
        uint32_t ahi0[4], ahi1[4], alo0[4], alo1[4];
        ldm_x4(ahi0, aAH + aoff + kb);
        ldm_x4(ahi1, aAH + aoff + kb + 16 * KPAD * 4);
        ldm_x4(alo0, aAL + aoff + kb);
        ldm_x4(alo1, aAL + aoff + kb + 16 * KPAD * 4);
#pragma unroll
        for (int p = 0; p < 4; p++) {
            uint32_t bh4[4], bl4[4];
            uint32_t bo = boff + kb + p * 16 * KPAD * 4;
            ldm_x4(bh4, aBH + bo);
            ldm_x4(bl4, aBL + bo);
#pragma unroll
            for (int q = 0; q < 2; q++) {
                int nt = p * 2 + q;
                mma_f16(acc[0][nt], ahi0, &bh4[q*2]);
                mma_f16(acc[0][nt], ahi0, &bl4[q*2]);
                mma_f16(acc[0][nt], alo0, &bh4[q*2]);
                mma_f16(acc[1][nt], ahi1, &bh4[q*2]);
                mma_f16(acc[1][nt], ahi1, &bl4[q*2]);
                mma_f16(acc[1][nt], alo1, &bh4[q*2]);
            }
        }
    }

    // Epilogue: write fp32 scores, accumulate per-row stats
#pragma unroll
    for (int mt = 0; mt < 2; mt++) {
        int r0 = wm * 32 + mt * 16 + g;
        int r1 = r0 + 8;
        float s2a = 0.f, s4a = 0.f, mxa = 0.f;
        float s2b = 0.f, s4b = 0.f, mxb = 0.f;
#pragma unroll
        for (int nt = 0; nt < 8; nt++) {
            float* cc = acc[mt][nt];
            float q0 = cc[0] * cc[0]; s2a += q0; s4a += q0 * q0; mxa = fmaxf(mxa, q0);
            float q1 = cc[1] * cc[1]; s2a += q1; s4a += q1 * q1; mxa = fmaxf(mxa, q1);
            float q2 = cc[2] * cc[2]; s2b += q2; s4b += q2 * q2; mxb = fmaxf(mxb, q2);
            float q3 = cc[3] * cc[3]; s2b += q3; s4b += q3 * q3; mxb = fmaxf(mxb, q3);
            int col = n0 + wn * 64 + nt * 8 + tg * 2;
            *(float2*)(C + (size_t)(m0 + r0) * SS + col) = make_float2(cc[0], cc[1]);
            *(float2*)(C + (size_t)(m0 + r1) * SS + col) = make_float2(cc[2], cc[3]);
        }
#pragma unroll
        for (int o = 1; o <= 2; o <<= 1) {
            s2a += __shfl_xor_sync(0xffffffffu, s2a, o);
            s4a += __shfl_xor_sync(0xffffffffu, s4a, o);
            mxa  = fmaxf(mxa, __shfl_xor_sync(0xffffffffu, mxa, o));
            s2b += __shfl_xor_sync(0xffffffffu, s2b, o);
            s4b += __shfl_xor_sync(0xffffffffu, s4b, o);
            mxb  = fmaxf(mxb, __shfl_xor_sync(0xffffffffu, mxb, o));
        }
        if (tg == 0) {
            int ga = bh * LL + m0 + r0;
            atomicAdd(&g_s2[ga], s2a);
            atomicAdd(&g_s4[ga], s4a);
            atomicMax(&g_mx[ga], __float_as_int(mxa));
            int gb = ga + 8;
            atomicAdd(&g_s2[gb], s2b);
            atomicAdd(&g_s4[gb], s4b);
            atomicMax(&g_mx[gb], __float_as_int(mxb));
        }
    }
}

// ---------------------------------------------------------------------------
// Phase C: AV with cp.async depth-2 pipeline. CTA tile 128(M=l) x 64(N=d),
// K=S in 64-chunks (16 iters). Scores stream global->smem async; exp+fp16
// conversion from smem; MMA via ldmatrix. Row sums per loader thread.
// ---------------------------------------------------------------------------
#define AST 68                              // fp32 stage row stride (floats)
#define OF_A32 0                            // 2 * 128*68*4 = 69632
#define A32_SLOT (128 * AST * 4)            // 34816
#define OF_AOP 69632                        // 128*36*4 = 18432
#define OF_B   88064                        // 2 * 64*36*4 = 18432
#define B_SLOT (64 * KPAD * 4)              // 9216
#define OF_RS  106496                       // 128 floats
#define AV_SMEM 107008

__global__ __launch_bounds__(256) void fa_av_mma(float* __restrict__ out)
{
    extern __shared__ char smc[];
    uint32_t sb = smem_u32(smc);

    int bh = blockIdx.y;
    int b = bh >> 3, h = bh & 7;
    int m0 = blockIdx.x * 128;
    const float* A = g_Sc + (size_t)bh * LL * SS;
    const uint32_t* Vt = g_VtH + (size_t)bh * DD * 512;

    int tid = threadIdx.x, wid = tid >> 5, lane = tid & 31;
    int g = lane >> 2, tg = lane & 3;
    int wm = wid & 3, wn = wid >> 2;

    // --- pipeline issue: stage ch into slot (A fp32 + B fp16) ---
    auto issue = [&](int ch, int slot) {
        if (ch < 16) {
            int k0 = ch * 64;
#pragma unroll
            for (int i = 0; i < 8; i++) {
                int idx = tid + i * 256;
                int row = idx >> 4, seg = idx & 15;
                cp16(sb + OF_A32 + slot * A32_SLOT + (uint32_t)(row * AST + seg * 4) * 4,
                     A + (size_t)(m0 + row) * SS + ch * 64 + seg * 4);
            }
#pragma unroll
            for (int i = 0; i < 2; i++) {
                int idx = tid + i * 256;
                int d = idx >> 3, seg = idx & 7;
                cp16(sb + OF_B + slot * B_SLOT + (uint32_t)(d * KPAD + seg * 4) * 4,
                     Vt + (size_t)d * 512 + (k0 >> 1) + seg * 4);
            }
        }
        cp_commit();
    };

    issue(0, 0);
    issue(1, 1);

    // per-thread row scalars (thread owns score row tid>>1)
    int myrow = tid >> 1;
    int o2 = tid & 1;
    int gr = bh * LL + m0 + myrow;
    float rs2 = g_s2[gr], rs4 = g_s4[gr];
    float cA = ((rs4 > 0.f) ? sqrtf(rs2) * rsqrtf(rs4) : 0.f) * LOG2E;
    float mA = cA * __int_as_float(g_mx[gr]);
    float rs = 0.f;

    // ldmatrix byte offsets
    int arow = wm * 32 + (lane & 15);
    uint32_t aoff = sb + OF_AOP + (uint32_t)(arow * KPAD + ((lane >> 4) << 2)) * 4;
    int brow = wn * 32 + ((lane >> 4) << 3) + (lane & 7);
    uint32_t boff = sb + OF_B + (uint32_t)(brow * KPAD + (((lane >> 3) & 1) << 2)) * 4;

    float acc[2][4][4];
#pragma unroll
    for (int mt = 0; mt < 2; mt++)
#pragma unroll
        for (int nt = 0; nt < 4; nt++)
#pragma unroll
            for (int j = 0; j < 4; j++) acc[mt][nt][j] = 0.f;

    for (int ch = 0; ch < 16; ch++) {
        int slot = ch & 1;
        CP_WAIT(1);
        __syncthreads();                 // stage ch data visible to all

        // convert: fp32 scores -> exp2 -> fp16 pairs in Aop
        {
            const float* a32 = (const float*)(smc + OF_A32 + slot * A32_SLOT)
                               + myrow * AST + o2 * 32;
            uint32_t* aop = (uint32_t*)(smc + OF_AOP) + myrow * KPAD + o2 * 16;
#pragma unroll
            for (int q = 0; q < 8; q++) {
                float4 v = *(const float4*)(a32 + q * 4);
                __half h0 = __float2half_rn(ex2f(fmaf(cA * v.x, v.x, -mA)));
                __half h1 = __float2half_rn(ex2f(fmaf(cA * v.y, v.y, -mA)));
                __half h2 = __float2half_rn(ex2f(fmaf(cA * v.z, v.z, -mA)));
                __half h3 = __float2half_rn(ex2f(fmaf(cA * v.w, v.w, -mA)));
                rs += (__half2float(h0) + __half2float(h1))
                    + (__half2float(h2) + __half2float(h3));
                *(uint2*)(aop + q * 2) = make_uint2(packh2(h0, h1), packh2(h2, h3));
            }
        }
        __syncthreads();                 // Aop ready

        // MMA over Aop x B[slot]
        uint32_t bslot = boff + slot * B_SLOT;
#pragma unroll
        for (int ks = 0; ks < 4; ks++) {
            uint32_t kb = ks * 32;
            uint32_t a0[4], a1[4];
            ldm_x4(a0, aoff + kb);
            ldm_x4(a1, aoff + kb + 16 * KPAD * 4);
#pragma unroll
            for (int p = 0; p < 2; p++) {
                uint32_t b4[4];
                ldm_x4(b4, bslot + kb + p * 16 * KPAD * 4);
#pragma unroll
                for (int q = 0; q < 2; q++) {
                    int nt = p * 2 + q;
                    mma_f16(acc[0][nt], a0, &b4[q*2]);
                    mma_f16(acc[1][nt], a1, &b4[q*2]);
                }
            }
        }
        __syncthreads();                 // stage fully consumed

        issue(ch + 2, slot);             // refill this slot
    }

    // Row sums: combine the two half-row threads
    {
        float v = rs + __shfl_xor_sync(0xffffffffu, rs, 1);
        if (o2 == 0) ((float*)(smc + OF_RS))[myrow] = v;
    }
    __syncthreads();

    // Normalize + scatter to out[b][l][h][d]  (FIXED epilogue: acc[mt] only,
    // rows r0/r1 within the CTA's 128-row tile — no r0+16 aliasing)
    float* rowsum = (float*)(smc + OF_RS);
#pragma unroll
    for (int mt = 0; mt < 2; mt++) {
        int r0 = wm * 32 + mt * 16 + g;
        int r1 = r0 + 8;
        float i0 = 1.f / rowsum[r0];
        float i1 = 1.f / rowsum[r1];
#pragma unroll
        for (int nt = 0; nt < 4; nt++) {
            int col = wn * 32 + nt * 8 + tg * 2;
            float* p0 = out + (((size_t)b * LL + m0 + r0) * HH + h) * DD + col;
            *(float2*)p0 = make_float2(acc[mt][nt][0] * i0, acc[mt][nt][1] * i0);
            float* p1 = out + (((size_t)b * LL + m0 + r1) * HH + h) * DD + col;
            *(float2*)p1 = make_float2(acc[mt][nt][2] * i1, acc[mt][nt][3] * i1);
        }
    }
}

// ---------------------------------------------------------------------------
extern "C" void kernel_launch(void* const* d_in, const int* in_sizes, int n_in,
                              void* d_out, int out_size)
{
    const float* q = (const float*)d_in[0];   // [B,L,H,E]
    const float* k = (const float*)d_in[1];   // [B,S,H,E]
    const float* v = (const float*)d_in[2];   // [B,S,H,D]
    float* out = (float*)d_out;               // [B,L,H,D]

    const int QK_SMEM = 4 * 128 * KPAD * 4;   // 73728
    cudaFuncSetAttribute(fa_qk_mma, cudaFuncAttributeMaxDynamicSharedMemorySize, QK_SMEM);
    cudaFuncSetAttribute(fa_av_mma, cudaFuncAttributeMaxDynamicSharedMemorySize, AV_SMEM);

    fa_phi_kernel<<<dim3(8192, 2), 256>>>(q, k);
    fa_vt_kernel<<<dim3(16, BH), 256>>>(v);
    fa_qk_mma<<<dim3(8, 8, BH), 256, QK_SMEM>>>();
    fa_av_mma<<<dim3(8, BH), 256, AV_SMEM>>>(out);
}

// round 11
// speedup vs baseline: 3.0211x; 1.0704x over previous
#include <cuda_runtime.h>
#include <cuda_fp16.h>
#include <math.h>
#include <cstdint>

// Problem constants
#define BB 8
#define LL 1024
#define HH 8
#define EE 64
#define SS 1024
#define DD 64
#define BH (BB*HH)    // 64
#define NROWS (BH*LL) // 65536

// Static scratch (allocation-free rule: __device__ globals)
__device__ uint32_t g_QpH[(size_t)NROWS * 32];    // phi(Q) hi  fp16-pairs [row][kw]
__device__ uint32_t g_QpL[(size_t)NROWS * 32];    // phi(Q) lo
__device__ uint32_t g_KpH[(size_t)NROWS * 32];    // phi(K) hi
__device__ uint32_t g_KpL[(size_t)NROWS * 32];    // phi(K) lo
__device__ uint32_t g_VtH[(size_t)BH * DD * 512]; // V^T fp16 [bh][d][sw]
__device__ float    g_Sc[(size_t)BH * LL * SS];   // 256 MB raw scores (fp32)
__device__ float    g_s2[NROWS];
__device__ float    g_s4[NROWS];
__device__ int      g_mx[NROWS];

// ---------------------------------------------------------------------------
// Helpers
// ---------------------------------------------------------------------------
__device__ __forceinline__ void mma_f16(float* d, const uint32_t* a, const uint32_t* b) {
    asm volatile(
        "mma.sync.aligned.m16n8k16.row.col.f32.f16.f16.f32 "
        "{%0,%1,%2,%3}, {%4,%5,%6,%7}, {%8,%9}, {%0,%1,%2,%3};"
        : "+f"(d[0]), "+f"(d[1]), "+f"(d[2]), "+f"(d[3])
        : "r"(a[0]), "r"(a[1]), "r"(a[2]), "r"(a[3]), "r"(b[0]), "r"(b[1]));
}
__device__ __forceinline__ void ldm_x4(uint32_t* r, uint32_t a) {
    asm volatile("ldmatrix.sync.aligned.m8n8.x4.shared.b16 {%0,%1,%2,%3}, [%4];"
        : "=r"(r[0]), "=r"(r[1]), "=r"(r[2]), "=r"(r[3]) : "r"(a));
}
__device__ __forceinline__ uint32_t smem_u32(const void* p) {
    uint32_t a;
    asm("{ .reg .u64 t; cvta.to.shared.u64 t, %1; cvt.u32.u64 %0, t; }" : "=r"(a) : "l"(p));
    return a;
}
__device__ __forceinline__ void cp16(uint32_t sdst, const void* gsrc) {
    asm volatile("cp.async.cg.shared.global [%0], [%1], 16;" :: "r"(sdst), "l"(gsrc));
}
__device__ __forceinline__ void cp_commit() {
    asm volatile("cp.async.commit_group;" ::: "memory");
}
#define CP_WAIT(N) asm volatile("cp.async.wait_group %0;" :: "n"(N) : "memory")

__device__ __forceinline__ uint32_t packh2(__half a, __half b) {
    return (uint32_t)__half_as_ushort(a) | ((uint32_t)__half_as_ushort(b) << 16);
}
__device__ __forceinline__ float ex2f(float x) {
    float y;
    asm("ex2.approx.f32 %0, %1;" : "=f"(y) : "f"(x));
    return y;
}
#define LOG2E 1.4426950408889634f

// ---------------------------------------------------------------------------
// Phase A: phi_p for Q (y==0) and K (y==1); outputs fp16 hi/lo planes.
// ---------------------------------------------------------------------------
__global__ __launch_bounds__(256) void fa_phi_kernel(const float* __restrict__ qin,
                                                     const float* __restrict__ kin)
{
    int warp = blockIdx.x * 8 + (threadIdx.x >> 5);
    int lane = threadIdx.x & 31;
    int isK  = blockIdx.y;
    if (warp >= NROWS) return;

    int b = warp / (LL * HH);
    int l = (warp / HH) % LL;
    int h = warp % HH;

    const float2* src = (const float2*)((isK ? kin : qin) + (size_t)warp * EE);
    float2 xx = src[lane];
    float x0 = fmaxf(xx.x, 0.f), x1 = fmaxf(xx.y, 0.f);
    float a0 = x0 * x0, a1 = x1 * x1;
    float s2 = a0 + a1;
    float s4 = a0 * a0 + a1 * a1;
#pragma unroll
    for (int o = 16; o > 0; o >>= 1) {
        s2 += __shfl_xor_sync(0xffffffffu, s2, o);
        s4 += __shfl_xor_sync(0xffffffffu, s4, o);
    }
    float scale = (s4 > 0.f) ? sqrtf(s2) * rsqrtf(s4) : 0.f;

    float y0 = scale * a0, y1 = scale * a1;
    __half h0 = __float2half_rn(y0);
    __half h1 = __float2half_rn(y1);
    __half l0 = __float2half_rn(y0 - __half2float(h0));
    __half l1 = __float2half_rn(y1 - __half2float(h1));

    size_t row = (size_t)(b * HH + h) * LL + l;
    uint32_t* dH = (isK ? g_KpH : g_QpH) + row * 32;
    uint32_t* dL = (isK ? g_KpL : g_QpL) + row * 32;
    dH[lane] = packh2(h0, h1);
    dL[lane] = packh2(l0, l1);

    if (!isK && lane == 0) {
        g_s2[warp] = 0.f;
        g_s4[warp] = 0.f;
        g_mx[warp] = 0;
    }
}

// ---------------------------------------------------------------------------
// V transpose + fp16 pack: V[b][s][h][d] -> g_VtH[bh][d][s/2] packed pairs.
// ---------------------------------------------------------------------------
__global__ __launch_bounds__(256) void fa_vt_kernel(const float* __restrict__ V)
{
    __shared__ float sm[64][68];
    int bh = blockIdx.y;
    int b = bh >> 3, h = bh & 7;
    int s0 = blockIdx.x * 64;
    int tid = threadIdx.x;

#pragma unroll
    for (int i = 0; i < 4; i++) {
        int idx = tid + i * 256;
        int sl  = idx >> 4;
        int c4  = idx & 15;
        float4 v = *(const float4*)(V + (((size_t)b * SS + s0 + sl) * HH + h) * DD + c4 * 4);
        sm[c4*4+0][sl] = v.x; sm[c4*4+1][sl] = v.y;
        sm[c4*4+2][sl] = v.z; sm[c4*4+3][sl] = v.w;
    }
    __syncthreads();

    uint32_t* dst = g_VtH + (size_t)bh * DD * 512 + (s0 >> 1);
#pragma unroll
    for (int i = 0; i < 8; i++) {
        int idx = tid + i * 256;
        int d = idx >> 5;
        int w = idx & 31;
        dst[(size_t)d * 512 + w] = packh2(__float2half_rn(sm[d][2*w]),
                                          __float2half_rn(sm[d][2*w + 1]));
    }
}

// ---------------------------------------------------------------------------
// Phase B: QK, 4 N-tiles per CTA, double-buffered cp.async K tiles.
// CTA: rows m0..m0+127, cols (4x+j)*128 for j=0..3. 8 warps (4M x 2N).
// Q planes resident; stats in registers, one atomic set per CTA.
// ---------------------------------------------------------------------------
#define QKP 36    // words per fp16 row (32 data + 4 pad)
// word offsets: AH 0, AL 128*36, B buf s at 2*128*36 + s*2*128*36 (BH, BL)
#define W_AL (128*QKP)
#define W_B0 (2*128*QKP)
#define W_BUF (2*128*QKP)
#define QK_SMEM ((2*128*QKP + 2*2*128*QKP) * 4)   // 110592

__global__ __launch_bounds__(256) void fa_qk_mma()
{
    extern __shared__ uint32_t sw[];
    uint32_t sb = smem_u32(sw);

    int bh = blockIdx.z;
    int m0 = blockIdx.y * 128;
    int nbase = blockIdx.x * 4;
    const uint32_t* qh = g_QpH + (size_t)bh * LL * 32;
    const uint32_t* ql = g_QpL + (size_t)bh * LL * 32;
    const uint32_t* kh = g_KpH + (size_t)bh * SS * 32;
    const uint32_t* kl = g_KpL + (size_t)bh * SS * 32;
    float* C = g_Sc + (size_t)bh * LL * SS;

    int tid = threadIdx.x, wid = tid >> 5, lane = tid & 31;
    int g = lane >> 2, tg = lane & 3;
    int wm = wid & 3, wn = wid >> 2;

    auto issueB = [&](int j, int buf) {
        if (j < 4) {
            int n0 = (nbase + j) * 128;
            uint32_t base = sb + (uint32_t)(W_B0 + buf * W_BUF) * 4;
#pragma unroll
            for (int i = 0; i < 4; i++) {
                int idx = tid + i * 256;
                int row = idx >> 3, seg = idx & 7;
                uint32_t so = (uint32_t)(row * QKP + seg * 4) * 4;
                cp16(base + so,                     kh + (size_t)(n0 + row) * 32 + seg * 4);
                cp16(base + (128*QKP)*4 + so,       kl + (size_t)(n0 + row) * 32 + seg * 4);
            }
        }
        cp_commit();
    };

    // prologue: A planes + B0 in group 0; B1 in group 1
    {
#pragma unroll
        for (int i = 0; i < 4; i++) {
            int idx = tid + i * 256;
            int row = idx >> 3, seg = idx & 7;
            uint32_t so = (uint32_t)(row * QKP + seg * 4) * 4;
            cp16(sb + so,               qh + (size_t)(m0 + row) * 32 + seg * 4);
            cp16(sb + W_AL * 4 + so,    ql + (size_t)(m0 + row) * 32 + seg * 4);
        }
        issueB(0, 0);
        issueB(1, 1);
    }

    // ldmatrix byte offsets (within a plane)
    int arow = wm * 32 + (lane & 15);
    uint32_t aoff = (uint32_t)(arow * QKP + ((lane >> 4) << 2)) * 4;
    int brow = wn * 64 + ((lane >> 4) << 3) + (lane & 7);
    uint32_t boff = (uint32_t)(brow * QKP + (((lane >> 3) & 1) << 2)) * 4;
    uint32_t aAH = sb, aAL = sb + W_AL * 4;

    float st2[2][2] = {{0,0},{0,0}};
    float st4[2][2] = {{0,0},{0,0}};
    float stm[2][2] = {{0,0},{0,0}};

    for (int j = 0; j < 4; j++) {
        CP_WAIT(1);
        __syncthreads();
        int buf = j & 1;
        uint32_t aBH = sb + (uint32_t)(W_B0 + buf * W_BUF) * 4;
        uint32_t aBL = aBH + (128*QKP)*4;

        float acc[2][8][4];
#pragma unroll
        for (int mt = 0; mt < 2; mt++)
#pragma unroll
            for (int nt = 0; nt < 8; nt++)
#pragma unroll
                for (int q = 0; q < 4; q++) acc[mt][nt][q] = 0.f;

#pragma unroll
        for (int ks = 0; ks < 4; ks++) {
            uint32_t kb = ks * 32;
            uint32_t ahi0[4], ahi1[4], alo0[4], alo1[4];
            ldm_x4(ahi0, aAH + aoff + kb);
            ldm_x4(ahi1, aAH + aoff + kb + 16 * QKP * 4);
            ldm_x4(alo0, aAL + aoff + kb);
            ldm_x4(alo1, aAL + aoff + kb + 16 * QKP * 4);
#pragma unroll
            for (int p = 0; p < 4; p++) {
                uint32_t bh4[4], bl4[4];
                uint32_t bo = boff + kb + p * 16 * QKP * 4;
                ldm_x4(bh4, aBH + bo);
                ldm_x4(bl4, aBL + bo);
#pragma unroll
                for (int q = 0; q < 2; q++) {
                    int nt = p * 2 + q;
                    mma_f16(acc[0][nt], ahi0, &bh4[q*2]);
                    mma_f16(acc[0][nt], ahi0, &bl4[q*2]);
                    mma_f16(acc[0][nt], alo0, &bh4[q*2]);
                    mma_f16(acc[1][nt], ahi1, &bh4[q*2]);
                    mma_f16(acc[1][nt], ahi1, &bl4[q*2]);
                    mma_f16(acc[1][nt], alo1, &bh4[q*2]);
                }
            }
        }
        __syncthreads();          // buf fully consumed by all warps
        issueB(j + 2, buf);       // prefetch overlaps epilogue below

        int n0 = (nbase + j) * 128;
#pragma unroll
        for (int mt = 0; mt < 2; mt++) {
            int r0 = wm * 32 + mt * 16 + g;
            int r1 = r0 + 8;
#pragma unroll
            for (int nt = 0; nt < 8; nt++) {
                float* cc = acc[mt][nt];
                float q0 = cc[0]*cc[0]; st2[mt][0] += q0; st4[mt][0] += q0*q0; stm[mt][0] = fmaxf(stm[mt][0], q0);
                float q1 = cc[1]*cc[1]; st2[mt][0] += q1; st4[mt][0] += q1*q1; stm[mt][0] = fmaxf(stm[mt][0], q1);
                float q2 = cc[2]*cc[2]; st2[mt][1] += q2; st4[mt][1] += q2*q2; stm[mt][1] = fmaxf(stm[mt][1], q2);
                float q3 = cc[3]*cc[3]; st2[mt][1] += q3; st4[mt][1] += q3*q3; stm[mt][1] = fmaxf(stm[mt][1], q3);
                int col = n0 + wn * 64 + nt * 8 + tg * 2;
                *(float2*)(C + (size_t)(m0 + r0) * SS + col) = make_float2(cc[0], cc[1]);
                *(float2*)(C + (size_t)(m0 + r1) * SS + col) = make_float2(cc[2], cc[3]);
            }
        }
    }

    // stats: reduce over tg lanes, one atomic set per CTA
#pragma unroll
    for (int mt = 0; mt < 2; mt++) {
        float s2a = st2[mt][0], s4a = st4[mt][0], mxa = stm[mt][0];
        float s2b = st2[mt][1], s4b = st4[mt][1], mxb = stm[mt][1];
#pragma unroll
        for (int o = 1; o <= 2; o <<= 1) {
            s2a += __shfl_xor_sync(0xffffffffu, s2a, o);
            s4a += __shfl_xor_sync(0xffffffffu, s4a, o);
            mxa  = fmaxf(mxa, __shfl_xor_sync(0xffffffffu, mxa, o));
            s2b += __shfl_xor_sync(0xffffffffu, s2b, o);
            s4b += __shfl_xor_sync(0xffffffffu, s4b, o);
            mxb  = fmaxf(mxb, __shfl_xor_sync(0xffffffffu, mxb, o));
        }
        if (tg == 0) {
            int ga = bh * LL + m0 + wm * 32 + mt * 16 + g;
            atomicAdd(&g_s2[ga], s2a);
            atomicAdd(&g_s4[ga], s4a);
            atomicMax(&g_mx[ga], __float_as_int(mxa));
            int gb = ga + 8;
            atomicAdd(&g_s2[gb], s2b);
            atomicAdd(&g_s4[gb], s4b);
            atomicMax(&g_mx[gb], __float_as_int(mxb));
        }
    }
}

// ---------------------------------------------------------------------------
// Phase C: AV, depth-4 cp.async ring of 32-column chunks, issue-before-process.
// CTA tile 128(M=l) x 64(N=d); 32 chunks over S=1024.
// ---------------------------------------------------------------------------
#define AVW 36                      // A32 stage row stride (floats)
#define BVW 20                      // B slot row stride (words)
#define APW 20                      // Aop row stride (words)
#define A32_SLOT (128 * AVW * 4)    // 18432
#define B_SLOT   (64 * BVW * 4)     // 5120
#define OF_A32 0                    // 4 slots: 73728
#define OF_B   73728                // 4 slots: 20480 -> 94208
#define OF_AOP 94208                // 128*20*4 = 10240 -> 104448
#define OF_RS  104448               // 512
#define AV_SMEM 104960

__global__ __launch_bounds__(256) void fa_av_mma(float* __restrict__ out)
{
    extern __shared__ char smc[];
    uint32_t sb = smem_u32(smc);

    int bh = blockIdx.y;
    int b = bh >> 3, h = bh & 7;
    int m0 = blockIdx.x * 128;
    const float* A = g_Sc + (size_t)bh * LL * SS;
    const uint32_t* Vt = g_VtH + (size_t)bh * DD * 512;

    int tid = threadIdx.x, wid = tid >> 5, lane = tid & 31;
    int g = lane >> 2, tg = lane & 3;
    int wm = wid & 3, wn = wid >> 2;

    auto issue = [&](int ch, int slot) {
        if (ch < 32) {
#pragma unroll
            for (int i = 0; i < 4; i++) {
                int idx = tid + i * 256;
                int row = idx >> 3, seg = idx & 7;
                cp16(sb + OF_A32 + slot * A32_SLOT + (uint32_t)(row * AVW + seg * 4) * 4,
                     A + (size_t)(m0 + row) * SS + ch * 32 + seg * 4);
            }
            {
                int d = tid >> 2, seg = tid & 3;
                cp16(sb + OF_B + slot * B_SLOT + (uint32_t)(d * BVW + seg * 4) * 4,
                     Vt + (size_t)d * 512 + ch * 16 + seg * 4);
            }
        }
        cp_commit();
    };

    issue(0, 0);
    issue(1, 1);
    issue(2, 2);

    // per-thread row scalars (thread owns half of score row tid>>1)
    int myrow = tid >> 1;
    int o2 = tid & 1;
    int gr = bh * LL + m0 + myrow;
    float rs2 = g_s2[gr], rs4 = g_s4[gr];
    float cA = ((rs4 > 0.f) ? sqrtf(rs2) * rsqrtf(rs4) : 0.f) * LOG2E;
    float mA = cA * __int_as_float(g_mx[gr]);
    float rs = 0.f;

    // ldmatrix byte offsets
    int arow = wm * 32 + (lane & 15);
    uint32_t aoff = sb + OF_AOP + (uint32_t)(arow * APW + ((lane >> 4) << 2)) * 4;
    int brow = wn * 32 + ((lane >> 4) << 3) + (lane & 7);
    uint32_t boff = (uint32_t)(brow * BVW + (((lane >> 3) & 1) << 2)) * 4;

    float acc[2][4][4];
#pragma unroll
    for (int mt = 0; mt < 2; mt++)
#pragma unroll
        for (int nt = 0; nt < 4; nt++)
#pragma unroll
            for (int q = 0; q < 4; q++) acc[mt][nt][q] = 0.f;

    for (int ch = 0; ch < 32; ch++) {
        int slot = ch & 3;
        CP_WAIT(2);
        __syncthreads();                 // chunk ch visible; mma(ch-1) done by all
        issue(ch + 3, (ch + 3) & 3);     // refill freed slot; overlaps processing

        // convert: fp32 scores -> exp2 -> fp16 pairs in Aop (16 values/thread)
        {
            const float* a32 = (const float*)(smc + OF_A32 + slot * A32_SLOT)
                               + myrow * AVW + o2 * 16;
            uint32_t* aop = (uint32_t*)(smc + OF_AOP) + myrow * APW + o2 * 8;
#pragma unroll
            for (int q = 0; q < 4; q++) {
                float4 v = *(const float4*)(a32 + q * 4);
                __half h0 = __float2half_rn(ex2f(fmaf(cA * v.x, v.x, -mA)));
                __half h1 = __float2half_rn(ex2f(fmaf(cA * v.y, v.y, -mA)));
                __half h2 = __float2half_rn(ex2f(fmaf(cA * v.z, v.z, -mA)));
                __half h3 = __float2half_rn(ex2f(fmaf(cA * v.w, v.w, -mA)));
                rs += (__half2float(h0) + __half2float(h1))
                    + (__half2float(h2) + __half2float(h3));
                *(uint2*)(aop + q * 2) = make_uint2(packh2(h0, h1), packh2(h2, h3));
            }
        }
        __syncthreads();                 // Aop ready

        uint32_t bslot = sb + OF_B + slot * B_SLOT + boff;
#pragma unroll
        for (int ks = 0; ks < 2; ks++) {
            uint32_t kb = ks * 32;
            uint32_t a0[4], a1[4];
            ldm_x4(a0, aoff + kb);
            ldm_x4(a1, aoff + kb + 16 * APW * 4);
#pragma unroll
            for (int p = 0; p < 2; p++) {
                uint32_t b4[4];
                ldm_x4(b4, bslot + kb + p * 16 * BVW * 4);
#pragma unroll
                for (int q = 0; q < 2; q++) {
                    int nt = p * 2 + q;
                    mma_f16(acc[0][nt], a0, &b4[q*2]);
                    mma_f16(acc[1][nt], a1, &b4[q*2]);
                }
            }
        }
        // no trailing sync: next iteration's top sync orders reuse
    }

    // Row sums: combine the two half-row threads
    {
        float v = rs + __shfl_xor_sync(0xffffffffu, rs, 1);
        if (o2 == 0) ((float*)(smc + OF_RS))[myrow] = v;
    }
    __syncthreads();

    // Normalize + scatter to out[b][l][h][d]
    float* rowsum = (float*)(smc + OF_RS);
#pragma unroll
    for (int mt = 0; mt < 2; mt++) {
        int r0 = wm * 32 + mt * 16 + g;
        int r1 = r0 + 8;
        float i0 = 1.f / rowsum[r0];
        float i1 = 1.f / rowsum[r1];
#pragma unroll
        for (int nt = 0; nt < 4; nt++) {
            int col = wn * 32 + nt * 8 + tg * 2;
            float* p0 = out + (((size_t)b * LL + m0 + r0) * HH + h) * DD + col;
            *(float2*)p0 = make_float2(acc[mt][nt][0] * i0, acc[mt][nt][1] * i0);
            float* p1 = out + (((size_t)b * LL + m0 + r1) * HH + h) * DD + col;
            *(float2*)p1 = make_float2(acc[mt][nt][2] * i1, acc[mt][nt][3] * i1);
        }
    }
}

// ---------------------------------------------------------------------------
extern "C" void kernel_launch(void* const* d_in, const int* in_sizes, int n_in,
                              void* d_out, int out_size)
{
    const float* q = (const float*)d_in[0];   // [B,L,H,E]
    const float* k = (const float*)d_in[1];   // [B,S,H,E]
    const float* v = (const float*)d_in[2];   // [B,S,H,D]
    float* out = (float*)d_out;               // [B,L,H,D]

    cudaFuncSetAttribute(fa_qk_mma, cudaFuncAttributeMaxDynamicSharedMemorySize, QK_SMEM);
    cudaFuncSetAttribute(fa_av_mma, cudaFuncAttributeMaxDynamicSharedMemorySize, AV_SMEM);

    fa_phi_kernel<<<dim3(8192, 2), 256>>>(q, k);
    fa_vt_kernel<<<dim3(16, BH), 256>>>(v);
    fa_qk_mma<<<dim3(2, 8, BH), 256, QK_SMEM>>>();
    fa_av_mma<<<dim3(8, BH), 256, AV_SMEM>>>(out);
}

// round 12
// speedup vs baseline: 3.0216x; 1.0002x over previous
#include <cuda_runtime.h>
#include <cuda_fp16.h>
#include <math.h>
#include <cstdint>

// Problem constants
#define BB 8
#define LL 1024
#define HH 8
#define EE 64
#define SS 1024
#define DD 64
#define BH (BB*HH)    // 64
#define NROWS (BH*LL) // 65536

// Static scratch (allocation-free rule: __device__ globals)
__device__ uint32_t g_QpH[(size_t)NROWS * 32];    // phi(Q) hi  fp16-pairs [row][kw]
__device__ uint32_t g_QpL[(size_t)NROWS * 32];    // phi(Q) lo
__device__ uint32_t g_KpH[(size_t)NROWS * 32];    // phi(K) hi
__device__ uint32_t g_KpL[(size_t)NROWS * 32];    // phi(K) lo
__device__ uint32_t g_VtH[(size_t)BH * DD * 512]; // V^T fp16 [bh][d][sw]
__device__ float    g_Sc[(size_t)BH * LL * SS];   // 256 MB raw scores (fp32)
__device__ float    g_s2[NROWS];
__device__ float    g_s4[NROWS];
__device__ int      g_mx[NROWS];

// ---------------------------------------------------------------------------
// Helpers
// ---------------------------------------------------------------------------
__device__ __forceinline__ void mma_f16(float* d, const uint32_t* a, const uint32_t* b) {
    asm volatile(
        "mma.sync.aligned.m16n8k16.row.col.f32.f16.f16.f32 "
        "{%0,%1,%2,%3}, {%4,%5,%6,%7}, {%8,%9}, {%0,%1,%2,%3};"
        : "+f"(d[0]), "+f"(d[1]), "+f"(d[2]), "+f"(d[3])
        : "r"(a[0]), "r"(a[1]), "r"(a[2]), "r"(a[3]), "r"(b[0]), "r"(b[1]));
}
__device__ __forceinline__ void ldm_x4(uint32_t* r, uint32_t a) {
    asm volatile("ldmatrix.sync.aligned.m8n8.x4.shared.b16 {%0,%1,%2,%3}, [%4];"
        : "=r"(r[0]), "=r"(r[1]), "=r"(r[2]), "=r"(r[3]) : "r"(a));
}
__device__ __forceinline__ uint32_t smem_u32(const void* p) {
    uint32_t a;
    asm("{ .reg .u64 t; cvta.to.shared.u64 t, %1; cvt.u32.u64 %0, t; }" : "=r"(a) : "l"(p));
    return a;
}
__device__ __forceinline__ void cp16(uint32_t sdst, const void* gsrc) {
    asm volatile("cp.async.cg.shared.global [%0], [%1], 16;" :: "r"(sdst), "l"(gsrc));
}
__device__ __forceinline__ void cp_commit() {
    asm volatile("cp.async.commit_group;" ::: "memory");
}
#define CP_WAIT(N) asm volatile("cp.async.wait_group %0;" :: "n"(N) : "memory")

__device__ __forceinline__ uint32_t packh2(__half a, __half b) {
    return (uint32_t)__half_as_ushort(a) | ((uint32_t)__half_as_ushort(b) << 16);
}
__device__ __forceinline__ float ex2f(float x) {
    float y;
    asm("ex2.approx.f32 %0, %1;" : "=f"(y) : "f"(x));
    return y;
}
#define LOG2E 1.4426950408889634f

// ---------------------------------------------------------------------------
// Phase A: phi_p for Q (y==0) and K (y==1); outputs fp16 hi/lo planes.
// ---------------------------------------------------------------------------
__global__ __launch_bounds__(256) void fa_phi_kernel(const float* __restrict__ qin,
                                                     const float* __restrict__ kin)
{
    int warp = blockIdx.x * 8 + (threadIdx.x >> 5);
    int lane = threadIdx.x & 31;
    int isK  = blockIdx.y;
    if (warp >= NROWS) return;

    int b = warp / (LL * HH);
    int l = (warp / HH) % LL;
    int h = warp % HH;

    const float2* src = (const float2*)((isK ? kin : qin) + (size_t)warp * EE);
    float2 xx = src[lane];
    float x0 = fmaxf(xx.x, 0.f), x1 = fmaxf(xx.y, 0.f);
    float a0 = x0 * x0, a1 = x1 * x1;
    float s2 = a0 + a1;
    float s4 = a0 * a0 + a1 * a1;
#pragma unroll
    for (int o = 16; o > 0; o >>= 1) {
        s2 += __shfl_xor_sync(0xffffffffu, s2, o);
        s4 += __shfl_xor_sync(0xffffffffu, s4, o);
    }
    float scale = (s4 > 0.f) ? sqrtf(s2) * rsqrtf(s4) : 0.f;

    float y0 = scale * a0, y1 = scale * a1;
    __half h0 = __float2half_rn(y0);
    __half h1 = __float2half_rn(y1);
    __half l0 = __float2half_rn(y0 - __half2float(h0));
    __half l1 = __float2half_rn(y1 - __half2float(h1));

    size_t row = (size_t)(b * HH + h) * LL + l;
    uint32_t* dH = (isK ? g_KpH : g_QpH) + row * 32;
    uint32_t* dL = (isK ? g_KpL : g_QpL) + row * 32;
    dH[lane] = packh2(h0, h1);
    dL[lane] = packh2(l0, l1);

    if (!isK && lane == 0) {
        g_s2[warp] = 0.f;
        g_s4[warp] = 0.f;
        g_mx[warp] = 0;
    }
}

// ---------------------------------------------------------------------------
// V transpose + fp16 pack: V[b][s][h][d] -> g_VtH[bh][d][s/2] packed pairs.
// ---------------------------------------------------------------------------
__global__ __launch_bounds__(256) void fa_vt_kernel(const float* __restrict__ V)
{
    __shared__ float sm[64][68];
    int bh = blockIdx.y;
    int b = bh >> 3, h = bh & 7;
    int s0 = blockIdx.x * 64;
    int tid = threadIdx.x;

#pragma unroll
    for (int i = 0; i < 4; i++) {
        int idx = tid + i * 256;
        int sl  = idx >> 4;
        int c4  = idx & 15;
        float4 v = *(const float4*)(V + (((size_t)b * SS + s0 + sl) * HH + h) * DD + c4 * 4);
        sm[c4*4+0][sl] = v.x; sm[c4*4+1][sl] = v.y;
        sm[c4*4+2][sl] = v.z; sm[c4*4+3][sl] = v.w;
    }
    __syncthreads();

    uint32_t* dst = g_VtH + (size_t)bh * DD * 512 + (s0 >> 1);
#pragma unroll
    for (int i = 0; i < 8; i++) {
        int idx = tid + i * 256;
        int d = idx >> 5;
        int w = idx & 31;
        dst[(size_t)d * 512 + w] = packh2(__float2half_rn(sm[d][2*w]),
                                          __float2half_rn(sm[d][2*w + 1]));
    }
}

// ---------------------------------------------------------------------------
// Phase B: QK, 4 N-tiles per CTA, double-buffered cp.async K tiles.
// (unchanged from R11; carveout hint added host-side for 2 CTAs/SM)
// ---------------------------------------------------------------------------
#define QKP 36    // words per fp16 row (32 data + 4 pad)
#define W_AL (128*QKP)
#define W_B0 (2*128*QKP)
#define W_BUF (2*128*QKP)
#define QK_SMEM ((2*128*QKP + 2*2*128*QKP) * 4)   // 110592

__global__ __launch_bounds__(256) void fa_qk_mma()
{
    extern __shared__ uint32_t sw[];
    uint32_t sb = smem_u32(sw);

    int bh = blockIdx.z;
    int m0 = blockIdx.y * 128;
    int nbase = blockIdx.x * 4;
    const uint32_t* qh = g_QpH + (size_t)bh * LL * 32;
    const uint32_t* ql = g_QpL + (size_t)bh * LL * 32;
    const uint32_t* kh = g_KpH + (size_t)bh * SS * 32;
    const uint32_t* kl = g_KpL + (size_t)bh * SS * 32;
    float* C = g_Sc + (size_t)bh * LL * SS;

    int tid = threadIdx.x, wid = tid >> 5, lane = tid & 31;
    int g = lane >> 2, tg = lane & 3;
    int wm = wid & 3, wn = wid >> 2;

    auto issueB = [&](int j, int buf) {
        if (j < 4) {
            int n0 = (nbase + j) * 128;
            uint32_t base = sb + (uint32_t)(W_B0 + buf * W_BUF) * 4;
#pragma unroll
            for (int i = 0; i < 4; i++) {
                int idx = tid + i * 256;
                int row = idx >> 3, seg = idx & 7;
                uint32_t so = (uint32_t)(row * QKP + seg * 4) * 4;
                cp16(base + so,                kh + (size_t)(n0 + row) * 32 + seg * 4);
                cp16(base + (128*QKP)*4 + so,  kl + (size_t)(n0 + row) * 32 + seg * 4);
            }
        }
        cp_commit();
    };

    {
#pragma unroll
        for (int i = 0; i < 4; i++) {
            int idx = tid + i * 256;
            int row = idx >> 3, seg = idx & 7;
            uint32_t so = (uint32_t)(row * QKP + seg * 4) * 4;
            cp16(sb + so,            qh + (size_t)(m0 + row) * 32 + seg * 4);
            cp16(sb + W_AL * 4 + so, ql + (size_t)(m0 + row) * 32 + seg * 4);
        }
        issueB(0, 0);
        issueB(1, 1);
    }

    int arow = wm * 32 + (lane & 15);
    uint32_t aoff = (uint32_t)(arow * QKP + ((lane >> 4) << 2)) * 4;
    int brow = wn * 64 + ((lane >> 4) << 3) + (lane & 7);
    uint32_t boff = (uint32_t)(brow * QKP + (((lane >> 3) & 1) << 2)) * 4;
    uint32_t aAH = sb, aAL = sb + W_AL * 4;

    float st2[2][2] = {{0,0},{0,0}};
    float st4[2][2] = {{0,0},{0,0}};
    float stm[2][2] = {{0,0},{0,0}};

    for (int j = 0; j < 4; j++) {
        CP_WAIT(1);
        __syncthreads();
        int buf = j & 1;
        uint32_t aBH = sb + (uint32_t)(W_B0 + buf * W_BUF) * 4;
        uint32_t aBL = aBH + (128*QKP)*4;

        float acc[2][8][4];
#pragma unroll
        for (int mt = 0; mt < 2; mt++)
#pragma unroll
            for (int nt = 0; nt < 8; nt++)
#pragma unroll
                for (int q = 0; q < 4; q++) acc[mt][nt][q] = 0.f;

#pragma unroll
        for (int ks = 0; ks < 4; ks++) {
            uint32_t kb = ks * 32;
            uint32_t ahi0[4], ahi1[4], alo0[4], alo1[4];
            ldm_x4(ahi0, aAH + aoff + kb);
            ldm_x4(ahi1, aAH + aoff + kb + 16 * QKP * 4);
            ldm_x4(alo0, aAL + aoff + kb);
            ldm_x4(alo1, aAL + aoff + kb + 16 * QKP * 4);
#pragma unroll
            for (int p = 0; p < 4; p++) {
                uint32_t bh4[4], bl4[4];
                uint32_t bo = boff + kb + p * 16 * QKP * 4;
                ldm_x4(bh4, aBH + bo);
                ldm_x4(bl4, aBL + bo);
#pragma unroll
                for (int q = 0; q < 2; q++) {
                    int nt = p * 2 + q;
                    mma_f16(acc[0][nt], ahi0, &bh4[q*2]);
                    mma_f16(acc[0][nt], ahi0, &bl4[q*2]);
                    mma_f16(acc[0][nt], alo0, &bh4[q*2]);
                    mma_f16(acc[1][nt], ahi1, &bh4[q*2]);
                    mma_f16(acc[1][nt], ahi1, &bl4[q*2]);
                    mma_f16(acc[1][nt], alo1, &bh4[q*2]);
                }
            }
        }
        __syncthreads();
        issueB(j + 2, buf);

        int n0 = (nbase + j) * 128;
#pragma unroll
        for (int mt = 0; mt < 2; mt++) {
            int r0 = wm * 32 + mt * 16 + g;
            int r1 = r0 + 8;
#pragma unroll
            for (int nt = 0; nt < 8; nt++) {
                float* cc = acc[mt][nt];
                float q0 = cc[0]*cc[0]; st2[mt][0] += q0; st4[mt][0] += q0*q0; stm[mt][0] = fmaxf(stm[mt][0], q0);
                float q1 = cc[1]*cc[1]; st2[mt][0] += q1; st4[mt][0] += q1*q1; stm[mt][0] = fmaxf(stm[mt][0], q1);
                float q2 = cc[2]*cc[2]; st2[mt][1] += q2; st4[mt][1] += q2*q2; stm[mt][1] = fmaxf(stm[mt][1], q2);
                float q3 = cc[3]*cc[3]; st2[mt][1] += q3; st4[mt][1] += q3*q3; stm[mt][1] = fmaxf(stm[mt][1], q3);
                int col = n0 + wn * 64 + nt * 8 + tg * 2;
                *(float2*)(C + (size_t)(m0 + r0) * SS + col) = make_float2(cc[0], cc[1]);
                *(float2*)(C + (size_t)(m0 + r1) * SS + col) = make_float2(cc[2], cc[3]);
            }
        }
    }

#pragma unroll
    for (int mt = 0; mt < 2; mt++) {
        float s2a = st2[mt][0], s4a = st4[mt][0], mxa = stm[mt][0];
        float s2b = st2[mt][1], s4b = st4[mt][1], mxb = stm[mt][1];
#pragma unroll
        for (int o = 1; o <= 2; o <<= 1) {
            s2a += __shfl_xor_sync(0xffffffffu, s2a, o);
            s4a += __shfl_xor_sync(0xffffffffu, s4a, o);
            mxa  = fmaxf(mxa, __shfl_xor_sync(0xffffffffu, mxa, o));
            s2b += __shfl_xor_sync(0xffffffffu, s2b, o);
            s4b += __shfl_xor_sync(0xffffffffu, s4b, o);
            mxb  = fmaxf(mxb, __shfl_xor_sync(0xffffffffu, mxb, o));
        }
        if (tg == 0) {
            int ga = bh * LL + m0 + wm * 32 + mt * 16 + g;
            atomicAdd(&g_s2[ga], s2a);
            atomicAdd(&g_s4[ga], s4a);
            atomicMax(&g_mx[ga], __float_as_int(mxa));
            int gb = ga + 8;
            atomicAdd(&g_s2[gb], s2b);
            atomicAdd(&g_s4[gb], s4b);
            atomicMax(&g_mx[gb], __float_as_int(mxb));
        }
    }
}

// ---------------------------------------------------------------------------
// Phase C: AV, CTA tile M=64 x N=64 (grid 16 x 64 = 1024 CTAs), depth-4
// cp.async ring of 32-column chunks. 8 warps as 2M x 4N. ~61 KB smem ->
// 3 CTAs/SM for latency hiding.
// ---------------------------------------------------------------------------
#define AVW 36                      // A32 stage row stride (floats)
#define BVW 20                      // B slot row stride (words)
#define APW 20                      // Aop row stride (words)
#define A32_SLOT (64 * AVW * 4)     // 9216
#define B_SLOT   (64 * BVW * 4)     // 5120
#define OF_A32 0                    // 4 slots: 36864
#define OF_B   36864                // 4 slots: 20480 -> 57344
#define OF_AOP 57344                // 64*20*4 = 5120 -> 62464
#define OF_RS  62464                // 256
#define AV_SMEM 62720

__global__ __launch_bounds__(256) void fa_av_mma(float* __restrict__ out)
{
    extern __shared__ char smc[];
    uint32_t sb = smem_u32(smc);

    int bh = blockIdx.y;
    int b = bh >> 3, h = bh & 7;
    int m0 = blockIdx.x * 64;
    const float* A = g_Sc + (size_t)bh * LL * SS;
    const uint32_t* Vt = g_VtH + (size_t)bh * DD * 512;

    int tid = threadIdx.x, wid = tid >> 5, lane = tid & 31;
    int g = lane >> 2, tg = lane & 3;
    int wm = wid & 1, wn = wid >> 1;          // 2M x 4N

    auto issue = [&](int ch, int slot) {
        if (ch < 32) {
#pragma unroll
            for (int i = 0; i < 2; i++) {
                int idx = tid + i * 256;      // 0..511
                int row = idx >> 3, seg = idx & 7;
                cp16(sb + OF_A32 + slot * A32_SLOT + (uint32_t)(row * AVW + seg * 4) * 4,
                     A + (size_t)(m0 + row) * SS + ch * 32 + seg * 4);
            }
            {
                int d = tid >> 2, seg = tid & 3;
                cp16(sb + OF_B + slot * B_SLOT + (uint32_t)(d * BVW + seg * 4) * 4,
                     Vt + (size_t)d * 512 + ch * 16 + seg * 4);
            }
        }
        cp_commit();
    };

    issue(0, 0);
    issue(1, 1);
    issue(2, 2);

    // per-thread row scalars: thread owns quarter of score row tid>>2
    int myrow = tid >> 2;     // 0..63
    int o4 = tid & 3;         // 0..3
    int gr = bh * LL + m0 + myrow;
    float rs2 = g_s2[gr], rs4 = g_s4[gr];
    float cA = ((rs4 > 0.f) ? sqrtf(rs2) * rsqrtf(rs4) : 0.f) * LOG2E;
    float mA = cA * __int_as_float(g_mx[gr]);
    float rs = 0.f;

    // ldmatrix byte offsets
    int arow = wm * 32 + (lane & 15);
    uint32_t aoff = sb + OF_AOP + (uint32_t)(arow * APW + ((lane >> 4) << 2)) * 4;
    int brow = wn * 16 + ((lane >> 4) << 3) + (lane & 7);
    uint32_t boff = (uint32_t)(brow * BVW + (((lane >> 3) & 1) << 2)) * 4;

    float acc[2][2][4];
#pragma unroll
    for (int mt = 0; mt < 2; mt++)
#pragma unroll
        for (int nt = 0; nt < 2; nt++)
#pragma unroll
            for (int q = 0; q < 4; q++) acc[mt][nt][q] = 0.f;

    for (int ch = 0; ch < 32; ch++) {
        int slot = ch & 3;
        CP_WAIT(2);
        __syncthreads();                 // chunk ch visible; mma(ch-1) done by all
        issue(ch + 3, (ch + 3) & 3);     // refill freed slot; overlaps processing

        // convert: fp32 scores -> exp2 -> fp16 pairs (8 values/thread)
        {
            const float* a32 = (const float*)(smc + OF_A32 + slot * A32_SLOT)
                               + myrow * AVW + o4 * 8;
            uint32_t* aop = (uint32_t*)(smc + OF_AOP) + myrow * APW + o4 * 4;
#pragma unroll
            for (int q = 0; q < 2; q++) {
                float4 v = *(const float4*)(a32 + q * 4);
                __half h0 = __float2half_rn(ex2f(fmaf(cA * v.x, v.x, -mA)));
                __half h1 = __float2half_rn(ex2f(fmaf(cA * v.y, v.y, -mA)));
                __half h2 = __float2half_rn(ex2f(fmaf(cA * v.z, v.z, -mA)));
                __half h3 = __float2half_rn(ex2f(fmaf(cA * v.w, v.w, -mA)));
                rs += (__half2float(h0) + __half2float(h1))
                    + (__half2float(h2) + __half2float(h3));
                *(uint2*)(aop + q * 2) = make_uint2(packh2(h0, h1), packh2(h2, h3));
            }
        }
        __syncthreads();                 // Aop ready

        uint32_t bslot = sb + OF_B + slot * B_SLOT + boff;
#pragma unroll
        for (int ks = 0; ks < 2; ks++) {
            uint32_t kb = ks * 32;
            uint32_t a0[4], a1[4];
            ldm_x4(a0, aoff + kb);
            ldm_x4(a1, aoff + kb + 16 * APW * 4);
            uint32_t b4[4];
            ldm_x4(b4, bslot + kb);
#pragma unroll
            for (int q = 0; q < 2; q++) {
                mma_f16(acc[0][q], a0, &b4[q*2]);
                mma_f16(acc[1][q], a1, &b4[q*2]);
            }
        }
        // no trailing sync: next iteration's top sync orders reuse
    }

    // Row sums: combine the four quarter-row threads
    {
        float v = rs;
        v += __shfl_xor_sync(0xffffffffu, v, 1);
        v += __shfl_xor_sync(0xffffffffu, v, 2);
        if (o4 == 0) ((float*)(smc + OF_RS))[myrow] = v;
    }
    __syncthreads();

    // Normalize + scatter to out[b][l][h][d]
    float* rowsum = (float*)(smc + OF_RS);
#pragma unroll
    for (int mt = 0; mt < 2; mt++) {
        int r0 = wm * 32 + mt * 16 + g;
        int r1 = r0 + 8;
        float i0 = 1.f / rowsum[r0];
        float i1 = 1.f / rowsum[r1];
#pragma unroll
        for (int nt = 0; nt < 2; nt++) {
            int col = wn * 16 + nt * 8 + tg * 2;
            float* p0 = out + (((size_t)b * LL + m0 + r0) * HH + h) * DD + col;
            *(float2*)p0 = make_float2(acc[mt][nt][0] * i0, acc[mt][nt][1] * i0);
            float* p1 = out + (((size_t)b * LL + m0 + r1) * HH + h) * DD + col;
            *(float2*)p1 = make_float2(acc[mt][nt][2] * i1, acc[mt][nt][3] * i1);
        }
    }
}

// ---------------------------------------------------------------------------
extern "C" void kernel_launch(void* const* d_in, const int* in_sizes, int n_in,
                              void* d_out, int out_size)
{
    const float* q = (const float*)d_in[0];   // [B,L,H,E]
    const float* k = (const float*)d_in[1];   // [B,S,H,E]
    const float* v = (const float*)d_in[2];   // [B,S,H,D]
    float* out = (float*)d_out;               // [B,L,H,D]

    cudaFuncSetAttribute(fa_qk_mma, cudaFuncAttributeMaxDynamicSharedMemorySize, QK_SMEM);
    cudaFuncSetAttribute(fa_av_mma, cudaFuncAttributeMaxDynamicSharedMemorySize, AV_SMEM);
    // Max carveout so 2 (QK) / 3 (AV) CTAs per SM fit in the 228KB unified L1
    cudaFuncSetAttribute(fa_qk_mma, cudaFuncAttributePreferredSharedMemoryCarveout, 100);
    cudaFuncSetAttribute(fa_av_mma, cudaFuncAttributePreferredSharedMemoryCarveout, 100);

    fa_phi_kernel<<<dim3(8192, 2), 256>>>(q, k);
    fa_vt_kernel<<<dim3(16, BH), 256>>>(v);
    fa_qk_mma<<<dim3(2, 8, BH), 256, QK_SMEM>>>();
    fa_av_mma<<<dim3(16, BH), 256, AV_SMEM>>>(out);
}

// round 14
// speedup vs baseline: 3.2139x; 1.0637x over previous
#include <cuda_runtime.h>
#include <cuda_fp16.h>
#include <math.h>
#include <cstdint>

// Problem constants
#define BB 8
#define LL 1024
#define HH 8
#define EE 64
#define SS 1024
#define DD 64
#define BH (BB*HH)    // 64
#define NROWS (BH*LL) // 65536

// Static scratch (allocation-free rule: __device__ globals)
__device__ uint32_t g_QpH[(size_t)NROWS * 32];    // phi(Q) hi  fp16-pairs [row][kw]
__device__ uint32_t g_QpL[(size_t)NROWS * 32];    // phi(Q) lo
__device__ uint32_t g_KpH[(size_t)NROWS * 32];    // phi(K) hi
__device__ uint32_t g_KpL[(size_t)NROWS * 32];    // phi(K) lo
__device__ uint32_t g_VtH[(size_t)BH * DD * 512]; // V^T fp16 [bh][d][sw]
__device__ float    g_Sc[(size_t)BH * LL * SS];   // 256 MB raw scores (fp32)
__device__ float    g_s2[NROWS];
__device__ float    g_s4[NROWS];
__device__ int      g_mx[NROWS];

// ---------------------------------------------------------------------------
// Helpers
// ---------------------------------------------------------------------------
__device__ __forceinline__ void mma_f16(float* d, const uint32_t* a, const uint32_t* b) {
    asm volatile(
        "mma.sync.aligned.m16n8k16.row.col.f32.f16.f16.f32 "
        "{%0,%1,%2,%3}, {%4,%5,%6,%7}, {%8,%9}, {%0,%1,%2,%3};"
        : "+f"(d[0]), "+f"(d[1]), "+f"(d[2]), "+f"(d[3])
        : "r"(a[0]), "r"(a[1]), "r"(a[2]), "r"(a[3]), "r"(b[0]), "r"(b[1]));
}
__device__ __forceinline__ void ldm_x4(uint32_t* r, uint32_t a) {
    asm volatile("ldmatrix.sync.aligned.m8n8.x4.shared.b16 {%0,%1,%2,%3}, [%4];"
        : "=r"(r[0]), "=r"(r[1]), "=r"(r[2]), "=r"(r[3]) : "r"(a));
}
__device__ __forceinline__ uint32_t smem_u32(const void* p) {
    uint32_t a;
    asm("{ .reg .u64 t; cvta.to.shared.u64 t, %1; cvt.u32.u64 %0, t; }" : "=r"(a) : "l"(p));
    return a;
}
__device__ __forceinline__ void cp16(uint32_t sdst, const void* gsrc) {
    asm volatile("cp.async.cg.shared.global [%0], [%1], 16;" :: "r"(sdst), "l"(gsrc));
}
__device__ __forceinline__ void cp_commit() {
    asm volatile("cp.async.commit_group;" ::: "memory");
}
#define CP_WAIT(N) asm volatile("cp.async.wait_group %0;" :: "n"(N) : "memory")

__device__ __forceinline__ uint32_t packh2(__half a, __half b) {
    return (uint32_t)__half_as_ushort(a) | ((uint32_t)__half_as_ushort(b) << 16);
}
__device__ __forceinline__ float ex2f(float x) {
    float y;
    asm("ex2.approx.f32 %0, %1;" : "=f"(y) : "f"(x));
    return y;
}
#define LOG2E 1.4426950408889634f

// ---------------------------------------------------------------------------
// Phase A: phi_p for Q (y==0) and K (y==1); outputs fp16 hi/lo planes.
// ---------------------------------------------------------------------------
__global__ __launch_bounds__(256) void fa_phi_kernel(const float* __restrict__ qin,
                                                     const float* __restrict__ kin)
{
    int warp = blockIdx.x * 8 + (threadIdx.x >> 5);
    int lane = threadIdx.x & 31;
    int isK  = blockIdx.y;
    if (warp >= NROWS) return;

    int b = warp / (LL * HH);
    int l = (warp / HH) % LL;
    int h = warp % HH;

    const float2* src = (const float2*)((isK ? kin : qin) + (size_t)warp * EE);
    float2 xx = src[lane];
    float x0 = fmaxf(xx.x, 0.f), x1 = fmaxf(xx.y, 0.f);
    float a0 = x0 * x0, a1 = x1 * x1;
    float s2 = a0 + a1;
    float s4 = a0 * a0 + a1 * a1;
#pragma unroll
    for (int o = 16; o > 0; o >>= 1) {
        s2 += __shfl_xor_sync(0xffffffffu, s2, o);
        s4 += __shfl_xor_sync(0xffffffffu, s4, o);
    }
    float scale = (s4 > 0.f) ? sqrtf(s2) * rsqrtf(s4) : 0.f;

    float y0 = scale * a0, y1 = scale * a1;
    __half h0 = __float2half_rn(y0);
    __half h1 = __float2half_rn(y1);
    __half l0 = __float2half_rn(y0 - __half2float(h0));
    __half l1 = __float2half_rn(y1 - __half2float(h1));

    size_t row = (size_t)(b * HH + h) * LL + l;
    uint32_t* dH = (isK ? g_KpH : g_QpH) + row * 32;
    uint32_t* dL = (isK ? g_KpL : g_QpL) + row * 32;
    dH[lane] = packh2(h0, h1);
    dL[lane] = packh2(l0, l1);

    if (!isK && lane == 0) {
        g_s2[warp] = 0.f;
        g_s4[warp] = 0.f;
        g_mx[warp] = 0;
    }
}

// ---------------------------------------------------------------------------
// V transpose + fp16 pack: V[b][s][h][d] -> g_VtH[bh][d][s/2] packed pairs.
// ---------------------------------------------------------------------------
__global__ __launch_bounds__(256) void fa_vt_kernel(const float* __restrict__ V)
{
    __shared__ float sm[64][68];
    int bh = blockIdx.y;
    int b = bh >> 3, h = bh & 7;
    int s0 = blockIdx.x * 64;
    int tid = threadIdx.x;

#pragma unroll
    for (int i = 0; i < 4; i++) {
        int idx = tid + i * 256;
        int sl  = idx >> 4;
        int c4  = idx & 15;
        float4 v = *(const float4*)(V + (((size_t)b * SS + s0 + sl) * HH + h) * DD + c4 * 4);
        sm[c4*4+0][sl] = v.x; sm[c4*4+1][sl] = v.y;
        sm[c4*4+2][sl] = v.z; sm[c4*4+3][sl] = v.w;
    }
    __syncthreads();

    uint32_t* dst = g_VtH + (size_t)bh * DD * 512 + (s0 >> 1);
#pragma unroll
    for (int i = 0; i < 8; i++) {
        int idx = tid + i * 256;
        int d = idx >> 5;
        int w = idx & 31;
        dst[(size_t)d * 512 + w] = packh2(__float2half_rn(sm[d][2*w]),
                                          __float2half_rn(sm[d][2*w + 1]));
    }
}

// ---------------------------------------------------------------------------
// Phase B: QK, 4 N-tiles per CTA, double-buffered cp.async K tiles.
// (unchanged from R12)
// ---------------------------------------------------------------------------
#define QKP 36    // words per fp16 row (32 data + 4 pad)
#define W_AL (128*QKP)
#define W_B0 (2*128*QKP)
#define W_BUF (2*128*QKP)
#define QK_SMEM ((2*128*QKP + 2*2*128*QKP) * 4)   // 110592

__global__ __launch_bounds__(256) void fa_qk_mma()
{
    extern __shared__ uint32_t sw[];
    uint32_t sb = smem_u32(sw);

    int bh = blockIdx.z;
    int m0 = blockIdx.y * 128;
    int nbase = blockIdx.x * 4;
    const uint32_t* qh = g_QpH + (size_t)bh * LL * 32;
    const uint32_t* ql = g_QpL + (size_t)bh * LL * 32;
    const uint32_t* kh = g_KpH + (size_t)bh * SS * 32;
    const uint32_t* kl = g_KpL + (size_t)bh * SS * 32;
    float* C = g_Sc + (size_t)bh * LL * SS;

    int tid = threadIdx.x, wid = tid >> 5, lane = tid & 31;
    int g = lane >> 2, tg = lane & 3;
    int wm = wid & 3, wn = wid >> 2;

    auto issueB = [&](int j, int buf) {
        if (j < 4) {
            int n0 = (nbase + j) * 128;
            uint32_t base = sb + (uint32_t)(W_B0 + buf * W_BUF) * 4;
#pragma unroll
            for (int i = 0; i < 4; i++) {
                int idx = tid + i * 256;
                int row = idx >> 3, seg = idx & 7;
                uint32_t so = (uint32_t)(row * QKP + seg * 4) * 4;
                cp16(base + so,                kh + (size_t)(n0 + row) * 32 + seg * 4);
                cp16(base + (128*QKP)*4 + so,  kl + (size_t)(n0 + row) * 32 + seg * 4);
            }
        }
        cp_commit();
    };

    {
#pragma unroll
        for (int i = 0; i < 4; i++) {
            int idx = tid + i * 256;
            int row = idx >> 3, seg = idx & 7;
            uint32_t so = (uint32_t)(row * QKP + seg * 4) * 4;
            cp16(sb + so,            qh + (size_t)(m0 + row) * 32 + seg * 4);
            cp16(sb + W_AL * 4 + so, ql + (size_t)(m0 + row) * 32 + seg * 4);
        }
        issueB(0, 0);
        issueB(1, 1);
    }

    int arow = wm * 32 + (lane & 15);
    uint32_t aoff = (uint32_t)(arow * QKP + ((lane >> 4) << 2)) * 4;
    int brow = wn * 64 + ((lane >> 4) << 3) + (lane & 7);
    uint32_t boff = (uint32_t)(brow * QKP + (((lane >> 3) & 1) << 2)) * 4;
    uint32_t aAH = sb, aAL = sb + W_AL * 4;

    float st2[2][2] = {{0,0},{0,0}};
    float st4[2][2] = {{0,0},{0,0}};
    float stm[2][2] = {{0,0},{0,0}};

    for (int j = 0; j < 4; j++) {
        CP_WAIT(1);
        __syncthreads();
        int buf = j & 1;
        uint32_t aBH = sb + (uint32_t)(W_B0 + buf * W_BUF) * 4;
        uint32_t aBL = aBH + (128*QKP)*4;

        float acc[2][8][4];
#pragma unroll
        for (int mt = 0; mt < 2; mt++)
#pragma unroll
            for (int nt = 0; nt < 8; nt++)
#pragma unroll
                for (int q = 0; q < 4; q++) acc[mt][nt][q] = 0.f;

#pragma unroll
        for (int ks = 0; ks < 4; ks++) {
            uint32_t kb = ks * 32;
            uint32_t ahi0[4], ahi1[4], alo0[4], alo1[4];
            ldm_x4(ahi0, aAH + aoff + kb);
            ldm_x4(ahi1, aAH + aoff + kb + 16 * QKP * 4);
            ldm_x4(alo0, aAL + aoff + kb);
            ldm_x4(alo1, aAL + aoff + kb + 16 * QKP * 4);
#pragma unroll
            for (int p = 0; p < 4; p++) {
                uint32_t bh4[4], bl4[4];
                uint32_t bo = boff + kb + p * 16 * QKP * 4;
                ldm_x4(bh4, aBH + bo);
                ldm_x4(bl4, aBL + bo);
#pragma unroll
                for (int q = 0; q < 2; q++) {
                    int nt = p * 2 + q;
                    mma_f16(acc[0][nt], ahi0, &bh4[q*2]);
                    mma_f16(acc[0][nt], ahi0, &bl4[q*2]);
                    mma_f16(acc[0][nt], alo0, &bh4[q*2]);
                    mma_f16(acc[1][nt], ahi1, &bh4[q*2]);
                    mma_f16(acc[1][nt], ahi1, &bl4[q*2]);
                    mma_f16(acc[1][nt], alo1, &bh4[q*2]);
                }
            }
        }
        __syncthreads();
        issueB(j + 2, buf);

        int n0 = (nbase + j) * 128;
#pragma unroll
        for (int mt = 0; mt < 2; mt++) {
            int r0 = wm * 32 + mt * 16 + g;
            int r1 = r0 + 8;
#pragma unroll
            for (int nt = 0; nt < 8; nt++) {
                float* cc = acc[mt][nt];
                float q0 = cc[0]*cc[0]; st2[mt][0] += q0; st4[mt][0] += q0*q0; stm[mt][0] = fmaxf(stm[mt][0], q0);
                float q1 = cc[1]*cc[1]; st2[mt][0] += q1; st4[mt][0] += q1*q1; stm[mt][0] = fmaxf(stm[mt][0], q1);
                float q2 = cc[2]*cc[2]; st2[mt][1] += q2; st4[mt][1] += q2*q2; stm[mt][1] = fmaxf(stm[mt][1], q2);
                float q3 = cc[3]*cc[3]; st2[mt][1] += q3; st4[mt][1] += q3*q3; stm[mt][1] = fmaxf(stm[mt][1], q3);
                int col = n0 + wn * 64 + nt * 8 + tg * 2;
                *(float2*)(C + (size_t)(m0 + r0) * SS + col) = make_float2(cc[0], cc[1]);
                *(float2*)(C + (size_t)(m0 + r1) * SS + col) = make_float2(cc[2], cc[3]);
            }
        }
    }

#pragma unroll
    for (int mt = 0; mt < 2; mt++) {
        float s2a = st2[mt][0], s4a = st4[mt][0], mxa = stm[mt][0];
        float s2b = st2[mt][1], s4b = st4[mt][1], mxb = stm[mt][1];
#pragma unroll
        for (int o = 1; o <= 2; o <<= 1) {
            s2a += __shfl_xor_sync(0xffffffffu, s2a, o);
            s4a += __shfl_xor_sync(0xffffffffu, s4a, o);
            mxa  = fmaxf(mxa, __shfl_xor_sync(0xffffffffu, mxa, o));
            s2b += __shfl_xor_sync(0xffffffffu, s2b, o);
            s4b += __shfl_xor_sync(0xffffffffu, s4b, o);
            mxb  = fmaxf(mxb, __shfl_xor_sync(0xffffffffu, mxb, o));
        }
        if (tg == 0) {
            int ga = bh * LL + m0 + wm * 32 + mt * 16 + g;
            atomicAdd(&g_s2[ga], s2a);
            atomicAdd(&g_s4[ga], s4a);
            atomicMax(&g_mx[ga], __float_as_int(mxa));
            int gb = ga + 8;
            atomicAdd(&g_s2[gb], s2b);
            atomicAdd(&g_s4[gb], s4b);
            atomicMax(&g_mx[gb], __float_as_int(mxb));
        }
    }
}

// ---------------------------------------------------------------------------
// Phase C: AV, register-resident A fragments (no fp16 smem stage, 1 sync/chunk).
// CTA tile 128(M=l) x 64(N=d); 8 warps as 8M x 1N: warp w owns rows w*16..+15,
// all 64 output cols. Scores cp.async-staged fp32; each thread LDSes exactly
// its mma fragment positions, exp2s in registers, feeds mma directly.
// Depth-4 ring of 32-column chunks.
// ---------------------------------------------------------------------------
#define AVW 40                      // A stage row stride (floats; 8g+2tg distinct mod 32)
#define BVW 20                      // V slot row stride (words)
#define A_SLOT (128 * AVW * 4)      // 20480
#define B_SLOT (64 * BVW * 4)       // 5120
#define OF_A 0                      // 4 slots: 81920
#define OF_B 81920                  // 4 slots: 20480 -> 102400
#define AV_SMEM 102400

__global__ __launch_bounds__(256) void fa_av_mma(float* __restrict__ out)
{
    extern __shared__ char smc[];
    uint32_t sb = smem_u32(smc);

    int bh = blockIdx.y;
    int b = bh >> 3, h = bh & 7;
    int m0 = blockIdx.x * 128;
    const float* A = g_Sc + (size_t)bh * LL * SS;
    const uint32_t* Vt = g_VtH + (size_t)bh * DD * 512;

    int tid = threadIdx.x, wid = tid >> 5, lane = tid & 31;
    int g = lane >> 2, tg = lane & 3;

    auto issue = [&](int ch, int slot) {
        if (ch < 32) {
#pragma unroll
            for (int i = 0; i < 4; i++) {
                int idx = tid + i * 256;      // 0..1023 = 128 rows x 8 segs
                int row = idx >> 3, seg = idx & 7;
                cp16(sb + OF_A + slot * A_SLOT + (uint32_t)(row * AVW + seg * 4) * 4,
                     A + (size_t)(m0 + row) * SS + ch * 32 + seg * 4);
            }
            {
                int d = tid >> 2, seg = tid & 3;
                cp16(sb + OF_B + slot * B_SLOT + (uint32_t)(d * BVW + seg * 4) * 4,
                     Vt + (size_t)d * 512 + ch * 16 + seg * 4);
            }
        }
        cp_commit();
    };

    issue(0, 0);
    issue(1, 1);
    issue(2, 2);

    // warp-owned rows
    int r0 = wid * 16 + g;
    int r1 = r0 + 8;
    int gr0 = bh * LL + m0 + r0;
    int gr1 = gr0 + 8;
    float s2a = g_s2[gr0], s4a = g_s4[gr0];
    float s2b = g_s2[gr1], s4b = g_s4[gr1];
    float c0 = ((s4a > 0.f) ? sqrtf(s2a) * rsqrtf(s4a) : 0.f) * LOG2E;
    float c1 = ((s4b > 0.f) ? sqrtf(s2b) * rsqrtf(s4b) : 0.f) * LOG2E;
    float mm0 = c0 * __int_as_float(g_mx[gr0]);
    float mm1 = c1 * __int_as_float(g_mx[gr1]);
    float rs0 = 0.f, rs1 = 0.f;

    // V ldmatrix byte offsets, one per 16-d block p
    uint32_t bofs[4];
#pragma unroll
    for (int p = 0; p < 4; p++) {
        int brow = p * 16 + ((lane >> 4) << 3) + (lane & 7);
        bofs[p] = (uint32_t)(brow * BVW + (((lane >> 3) & 1) << 2)) * 4;
    }

    float acc[8][4];
#pragma unroll
    for (int nt = 0; nt < 8; nt++)
#pragma unroll
        for (int q = 0; q < 4; q++) acc[nt][q] = 0.f;

    for (int ch = 0; ch < 32; ch++) {
        int slot = ch & 3;
        CP_WAIT(2);
        __syncthreads();                 // chunk ch staged; chunk ch-1 consumed by all
        issue(ch + 3, (ch + 3) & 3);     // refill the slot freed last iteration

        const float* base = (const float*)(smc + OF_A + slot * A_SLOT);
        uint32_t bbase = sb + OF_B + slot * B_SLOT;

#pragma unroll
        for (int ks = 0; ks < 2; ks++) {
            // A fragments: LDS fp32 pairs -> exp2 -> fp16 pack in registers
            const float* p0 = base + r0 * AVW + ks * 16 + 2 * tg;
            const float* p1 = base + r1 * AVW + ks * 16 + 2 * tg;
            float2 v00 = *(const float2*)p0;
            float2 v01 = *(const float2*)(p0 + 8);
            float2 v10 = *(const float2*)p1;
            float2 v11 = *(const float2*)(p1 + 8);
            __half e00 = __float2half_rn(ex2f(fmaf(c0 * v00.x, v00.x, -mm0)));
            __half e01 = __float2half_rn(ex2f(fmaf(c0 * v00.y, v00.y, -mm0)));
            __half e02 = __float2half_rn(ex2f(fmaf(c0 * v01.x, v01.x, -mm0)));
            __half e03 = __float2half_rn(ex2f(fmaf(c0 * v01.y, v01.y, -mm0)));
            __half e10 = __float2half_rn(ex2f(fmaf(c1 * v10.x, v10.x, -mm1)));
            __half e11 = __float2half_rn(ex2f(fmaf(c1 * v10.y, v10.y, -mm1)));
            __half e12 = __float2half_rn(ex2f(fmaf(c1 * v11.x, v11.x, -mm1)));
            __half e13 = __float2half_rn(ex2f(fmaf(c1 * v11.y, v11.y, -mm1)));
            rs0 += (__half2float(e00) + __half2float(e01))
                 + (__half2float(e02) + __half2float(e03));
            rs1 += (__half2float(e10) + __half2float(e11))
                 + (__half2float(e12) + __half2float(e13));
            uint32_t a[4];
            a[0] = packh2(e00, e01);      // row r0, k = 2tg..2tg+1
            a[1] = packh2(e10, e11);      // row r1
            a[2] = packh2(e02, e03);      // row r0, k+8
            a[3] = packh2(e12, e13);      // row r1, k+8

            uint32_t kb = ks * 32;
#pragma unroll
            for (int p = 0; p < 4; p++) {
                uint32_t b4[4];
                ldm_x4(b4, bbase + bofs[p] + kb);
                mma_f16(acc[p*2],     a, &b4[0]);
                mma_f16(acc[p*2 + 1], a, &b4[2]);
            }
        }
        // single sync per chunk: next iteration's top sync orders slot reuse
    }

    // Row sums: butterfly over the 4 tg lanes (rows are warp-exclusive)
    rs0 += __shfl_xor_sync(0xffffffffu, rs0, 1);
    rs0 += __shfl_xor_sync(0xffffffffu, rs0, 2);
    rs1 += __shfl_xor_sync(0xffffffffu, rs1, 1);
    rs1 += __shfl_xor_sync(0xffffffffu, rs1, 2);
    float i0 = 1.f / rs0;
    float i1 = 1.f / rs1;

    // Normalize + scatter to out[b][l][h][d]
    float* o0 = out + (((size_t)b * LL + m0 + r0) * HH + h) * DD;
    float* o1 = out + (((size_t)b * LL + m0 + r1) * HH + h) * DD;
#pragma unroll
    for (int nt = 0; nt < 8; nt++) {
        int col = nt * 8 + tg * 2;
        *(float2*)(o0 + col) = make_float2(acc[nt][0] * i0, acc[nt][1] * i0);
        *(float2*)(o1 + col) = make_float2(acc[nt][2] * i1, acc[nt][3] * i1);
    }
}

// ---------------------------------------------------------------------------
extern "C" void kernel_launch(void* const* d_in, const int* in_sizes, int n_in,
                              void* d_out, int out_size)
{
    const float* q = (const float*)d_in[0];   // [B,L,H,E]
    const float* k = (const float*)d_in[1];   // [B,S,H,E]
    const float* v = (const float*)d_in[2];   // [B,S,H,D]
    float* out = (float*)d_out;               // [B,L,H,D]

    cudaFuncSetAttribute(fa_qk_mma, cudaFuncAttributeMaxDynamicSharedMemorySize, QK_SMEM);
    cudaFuncSetAttribute(fa_av_mma, cudaFuncAttributeMaxDynamicSharedMemorySize, AV_SMEM);
    cudaFuncSetAttribute(fa_qk_mma, cudaFuncAttributePreferredSharedMemoryCarveout, 100);
    cudaFuncSetAttribute(fa_av_mma, cudaFuncAttributePreferredSharedMemoryCarveout, 100);

    fa_phi_kernel<<<dim3(8192, 2), 256>>>(q, k);
    fa_vt_kernel<<<dim3(16, BH), 256>>>(v);
    fa_qk_mma<<<dim3(2, 8, BH), 256, QK_SMEM>>>();
    fa_av_mma<<<dim3(8, BH), 256, AV_SMEM>>>(out);
}